// round 9
// baseline (speedup 1.0000x reference)
#include <cuda_runtime.h>
#include <cuda_bf16.h>
#include <cstdint>
#include <cstddef>

// Problem constants
#define BB 2
#define TT 2048
#define CC 1024
#define HH 16
#define DD 64
#define NEGINF (-1e10f)

// ---------------------------------------------------------------------------
// Device-global scratch (no allocation allowed). q/k/v/y live ONLY as
// pre-split bf16 hi/lo pairs.
// ---------------------------------------------------------------------------
__device__ __nv_bfloat16 g_qh[(size_t)BB * HH * TT * DD];
__device__ __nv_bfloat16 g_ql[(size_t)BB * HH * TT * DD];
__device__ __nv_bfloat16 g_kh[(size_t)BB * HH * TT * DD];
__device__ __nv_bfloat16 g_kl[(size_t)BB * HH * TT * DD];
__device__ __nv_bfloat16 g_vh[(size_t)BB * HH * TT * DD];
__device__ __nv_bfloat16 g_vl[(size_t)BB * HH * TT * DD];
__device__ __nv_bfloat16 g_yh[(size_t)BB * TT * CC];
__device__ __nv_bfloat16 g_yl[(size_t)BB * TT * CC];

__device__ __nv_bfloat16 g_xh[(size_t)BB * TT * CC];
__device__ __nv_bfloat16 g_xl[(size_t)BB * TT * CC];
__device__ __nv_bfloat16 g_wah[(size_t)3 * CC * CC];
__device__ __nv_bfloat16 g_wal[(size_t)3 * CC * CC];
__device__ __nv_bfloat16 g_wph[(size_t)CC * CC];
__device__ __nv_bfloat16 g_wpl[(size_t)CC * CC];

// ---------------------------------------------------------------------------
// PTX helpers (sm_80+ — legal on plain sm_100 target)
// ---------------------------------------------------------------------------
__device__ __forceinline__ uint32_t smem_u32(const void* p) {
    return (uint32_t)__cvta_generic_to_shared(p);
}
__device__ __forceinline__ void cp16(uint32_t s, const void* g) {
    asm volatile("cp.async.cg.shared.global [%0], [%1], 16;" :: "r"(s), "l"(g));
}
__device__ __forceinline__ void cp_commit() {
    asm volatile("cp.async.commit_group;" ::: "memory");
}
template <int N>
__device__ __forceinline__ void cp_wait() {
    asm volatile("cp.async.wait_group %0;" :: "n"(N) : "memory");
}
__device__ __forceinline__ void ldmatrix_x4(uint32_t* r, uint32_t addr) {
    asm volatile("ldmatrix.sync.aligned.m8n8.x4.shared.b16 {%0,%1,%2,%3}, [%4];"
                 : "=r"(r[0]), "=r"(r[1]), "=r"(r[2]), "=r"(r[3]) : "r"(addr));
}
__device__ __forceinline__ void ldmatrix_x4_trans(uint32_t* r, uint32_t addr) {
    asm volatile("ldmatrix.sync.aligned.m8n8.x4.trans.shared.b16 {%0,%1,%2,%3}, [%4];"
                 : "=r"(r[0]), "=r"(r[1]), "=r"(r[2]), "=r"(r[3]) : "r"(addr));
}
__device__ __forceinline__ void mma_bf16(float* d, const uint32_t* a,
                                         const uint32_t* b) {
    asm volatile(
        "mma.sync.aligned.m16n8k16.row.col.f32.bf16.bf16.f32 "
        "{%0,%1,%2,%3}, {%4,%5,%6,%7}, {%8,%9}, {%0,%1,%2,%3};"
        : "+f"(d[0]), "+f"(d[1]), "+f"(d[2]), "+f"(d[3])
        : "r"(a[0]), "r"(a[1]), "r"(a[2]), "r"(a[3]), "r"(b[0]), "r"(b[1]));
}
// pack two f32 as bf16x2: first arg -> low half
__device__ __forceinline__ uint32_t pack_bf16(float lo, float hi) {
    uint32_t r;
    asm("cvt.rn.bf16x2.f32 %0, %1, %2;" : "=r"(r) : "f"(hi), "f"(lo));
    return r;
}

// ---------------------------------------------------------------------------
// Convert kernels: fp32 -> (bf16 hi, bf16 lo)
// ---------------------------------------------------------------------------
__global__ void split_kernel(const float* __restrict__ src,
                             __nv_bfloat16* __restrict__ hi,
                             __nv_bfloat16* __restrict__ lo, int n)
{
    int i = blockIdx.x * blockDim.x + threadIdx.x;
    if (i < n) {
        float v = src[i];
        __nv_bfloat16 h = __float2bfloat16(v);
        hi[i] = h;
        lo[i] = __float2bfloat16(v - __bfloat162float(h));
    }
}

__global__ void transpose_split_kernel(const float* __restrict__ src,
                                       __nv_bfloat16* __restrict__ hi,
                                       __nv_bfloat16* __restrict__ lo,
                                       int K, int N)
{
    __shared__ float tile[32][33];
    const int k0 = blockIdx.y * 32;
    const int n0 = blockIdx.x * 32;
    const int tx = threadIdx.x, ty = threadIdx.y;  // (32, 8)
#pragma unroll
    for (int i = ty; i < 32; i += 8)
        tile[i][tx] = src[(size_t)(k0 + i) * N + n0 + tx];
    __syncthreads();
#pragma unroll
    for (int i = ty; i < 32; i += 8) {
        float v = tile[tx][i];
        __nv_bfloat16 h = __float2bfloat16(v);
        size_t o = (size_t)(n0 + i) * K + k0 + tx;
        hi[o] = h;
        lo[o] = __float2bfloat16(v - __bfloat162float(h));
    }
}

// ---------------------------------------------------------------------------
// 3-stage cp.async mma.sync bf16 3-pass GEMM.
// CTA tile 128x128, BK=32, 8 warps. Per stage: A and B each 128 rows x 128B
// (hi bytes [0,64), lo [64,128)), SW128 swizzle (chunk ^= row&7).
// Stage = 32KB; 3 stages = 96KB; prefetch distance 2, cp_wait<1>.
// ---------------------------------------------------------------------------
#define BK 32
#define G_ABUF 16384
#define G_STAGE (2 * G_ABUF)       // 32768
#define GEMM_SMEM (3 * G_STAGE)    // 98304

__device__ __forceinline__ void g2_load(
    uint32_t st,
    const __nv_bfloat16* Ahi, const __nv_bfloat16* Alo,
    const __nv_bfloat16* Bhi, const __nv_bfloat16* Blo,
    int m0, int n0, int k0, int tid, int part)
{
    const int r = tid >> 1;
    const int hilo = tid & 1;
    const __nv_bfloat16* src = part ? (hilo ? Blo : Bhi)
                                    : (hilo ? Alo : Ahi);
    const int rbase = part ? n0 : m0;
    const uint32_t rowoff = st + (uint32_t)part * G_ABUF + (uint32_t)r * 128;
    const int rx = r & 7;
    const __nv_bfloat16* g = src + (size_t)(rbase + r) * CC + k0;
#pragma unroll
    for (int c = 0; c < 4; c++) {
        const int ch = hilo * 4 + c;
        cp16(rowoff + ((uint32_t)(ch ^ rx) << 4), g + c * 8);
    }
}

__global__ __launch_bounds__(256, 2) void tc_gemm_kernel(
    const __nv_bfloat16* __restrict__ Ahi, const __nv_bfloat16* __restrict__ Alo,
    const __nv_bfloat16* __restrict__ Bhi, const __nv_bfloat16* __restrict__ Blo,
    const float* __restrict__ bias, float* __restrict__ Cout,
    int N, int mode)
{
    extern __shared__ __align__(128) char dsm[];
    const uint32_t sb0 = smem_u32(dsm);

    const int tid = threadIdx.x;
    const int warp = tid >> 5;
    const int lane = tid & 31;
    const int warpM = warp >> 2;
    const int warpN = warp & 3;
    const int m0 = blockIdx.y * 128;
    const int n0 = blockIdx.x * 128;

    float acc[4][4][4];
#pragma unroll
    for (int mt = 0; mt < 4; mt++)
#pragma unroll
        for (int nt = 0; nt < 4; nt++)
#pragma unroll
            for (int i = 0; i < 4; i++) acc[mt][nt][i] = 0.0f;

    const int aRow = warpM * 64 + (lane & 15);
    const int aCh  = lane >> 4;
    const int rxA  = aRow & 7;
    const int bRow = warpN * 32 + (lane >> 4) * 8 + (lane & 7);
    const int bCh  = (lane >> 3) & 1;
    const int rxB  = bRow & 7;

    const int NCH = CC / BK;   // 32

    g2_load(sb0, Ahi, Alo, Bhi, Blo, m0, n0, 0, tid, 0);
    g2_load(sb0, Ahi, Alo, Bhi, Blo, m0, n0, 0, tid, 1);
    cp_commit();
    g2_load(sb0 + G_STAGE, Ahi, Alo, Bhi, Blo, m0, n0, BK, tid, 0);
    g2_load(sb0 + G_STAGE, Ahi, Alo, Bhi, Blo, m0, n0, BK, tid, 1);
    cp_commit();

    int s_cur = 0;
    for (int ch = 0; ch < NCH; ch++) {
        cp_wait<1>();
        __syncthreads();

        const uint32_t st = sb0 + (uint32_t)s_cur * G_STAGE;
        const uint32_t stB = st + G_ABUF;
        int s_pf = s_cur + 2; if (s_pf >= 3) s_pf -= 3;
        const uint32_t pb = sb0 + (uint32_t)s_pf * G_STAGE;
        const bool dopf = (ch + 2 < NCH);

#pragma unroll
        for (int ks = 0; ks < 2; ks++) {
            const int kch = ks * 2;
            uint32_t afh[4][4], afl[4][4], bfh[2][4], bfl[2][4];
#pragma unroll
            for (int mt = 0; mt < 4; mt++) {
                const uint32_t rowo = st + (uint32_t)(aRow + mt * 16) * 128;
                const int chh = aCh + kch;
                ldmatrix_x4(afh[mt], rowo + ((uint32_t)(chh ^ rxA) << 4));
                ldmatrix_x4(afl[mt], rowo + ((uint32_t)((chh + 4) ^ rxA) << 4));
            }
#pragma unroll
            for (int bp = 0; bp < 2; bp++) {
                const uint32_t rowo = stB + (uint32_t)(bRow + bp * 16) * 128;
                const int chh = bCh + kch;
                ldmatrix_x4(bfh[bp], rowo + ((uint32_t)(chh ^ rxB) << 4));
                ldmatrix_x4(bfl[bp], rowo + ((uint32_t)((chh + 4) ^ rxB) << 4));
            }

            if (dopf)
                g2_load(pb, Ahi, Alo, Bhi, Blo, m0, n0, (ch + 2) * BK, tid, ks);
            if (ks == 1) cp_commit();

#pragma unroll
            for (int mt = 0; mt < 4; mt++)
#pragma unroll
                for (int nt = 0; nt < 4; nt++)
                    mma_bf16(acc[mt][nt], afh[mt], bfh[nt >> 1] + (nt & 1) * 2);
#pragma unroll
            for (int mt = 0; mt < 4; mt++)
#pragma unroll
                for (int nt = 0; nt < 4; nt++)
                    mma_bf16(acc[mt][nt], afh[mt], bfl[nt >> 1] + (nt & 1) * 2);
#pragma unroll
            for (int mt = 0; mt < 4; mt++)
#pragma unroll
                for (int nt = 0; nt < 4; nt++)
                    mma_bf16(acc[mt][nt], afl[mt], bfh[nt >> 1] + (nt & 1) * 2);
        }
        if (++s_cur == 3) s_cur = 0;
    }

    // epilogue
#pragma unroll
    for (int mt = 0; mt < 4; mt++) {
#pragma unroll
        for (int i = 0; i < 2; i++) {
            const int m = m0 + warpM * 64 + mt * 16 + (lane >> 2) + i * 8;
            const int b = m >> 11;
            const int t = m & 2047;
#pragma unroll
            for (int nt = 0; nt < 4; nt++) {
                const int n = n0 + warpN * 32 + nt * 8 + (lane & 3) * 2;
                const float v0 = acc[mt][nt][i * 2 + 0] + bias[n];
                const float v1 = acc[mt][nt][i * 2 + 1] + bias[n + 1];
                if (mode == 0) {
                    const int region = n >> 10;      // 0=q 1=k 2=v
                    const int cc = n & 1023;
                    const int h = cc >> 6;
                    const int dd = cc & 63;
                    __nv_bfloat16* dh = (region == 0) ? g_qh
                                      : (region == 1) ? g_kh : g_vh;
                    __nv_bfloat16* dl = (region == 0) ? g_ql
                                      : (region == 1) ? g_kl : g_vl;
                    const size_t o = (((size_t)b * HH + h) * TT + t) * DD + dd;
                    const float h0 = __bfloat162float(__float2bfloat16(v0));
                    const float h1 = __bfloat162float(__float2bfloat16(v1));
                    *(uint32_t*)(dh + o) = pack_bf16(v0, v1);
                    *(uint32_t*)(dl + o) = pack_bf16(v0 - h0, v1 - h1);
                } else {
                    float2 w; w.x = v0; w.y = v1;
                    *(float2*)(Cout + (size_t)m * N + n) = w;
                }
            }
        }
    }
}

// ---------------------------------------------------------------------------
// cp.async double-buffered tensor-core flash attention (hi/lo compensated).
// Unchanged from Round 7/8 (passing, rel_err 1.66e-5).
// ---------------------------------------------------------------------------
#define KVROW 72
#define A_BUF (64 * KVROW * 2)
#define A_STAGE (4 * A_BUF + 256)
#define ATTN_SMEM (2 * A_STAGE)

__device__ __forceinline__ void attn_stage_load(
    uint32_t sb,
    const __nv_bfloat16* Kh, const __nv_bfloat16* Kl,
    const __nv_bfloat16* Vh, const __nv_bfloat16* Vl,
    const float* amp, int k0, int tid)
{
    const int r = tid >> 2;
    const int s2 = (tid & 3) * 2;
#pragma unroll
    for (int i = 0; i < 2; i++) {
        const int seg = s2 + i;
        const uint32_t so = (uint32_t)(r * KVROW + seg * 8) * 2;
        const size_t go = (size_t)(k0 + r) * DD + seg * 8;
        cp16(sb + 0 * A_BUF + so, Kh + go);
        cp16(sb + 1 * A_BUF + so, Kl + go);
        cp16(sb + 2 * A_BUF + so, Vh + go);
        cp16(sb + 3 * A_BUF + so, Vl + go);
    }
    if (tid < 16) cp16(sb + 4 * A_BUF + tid * 16, amp + k0 + tid * 4);
}

__global__ __launch_bounds__(256) void attn_tc_kernel(const float* __restrict__ am)
{
    extern __shared__ __align__(16) char dsm[];
    const uint32_t sb0 = smem_u32(dsm);

    const int tid = threadIdx.x;
    const int warp = tid >> 5;
    const int lane = tid & 31;
    const int g = lane >> 2;
    const int c = lane & 3;
    const int bh = blockIdx.y;
    const int b = bh >> 4;
    const int h = bh & 15;
    const int qtile = gridDim.x - 1 - blockIdx.x;
    const int q0 = qtile * 128;

    const int r1 = q0 + warp * 16 + g;
    const int r2 = r1 + 8;

    const __nv_bfloat16* Qh = g_qh + (size_t)bh * TT * DD;
    const __nv_bfloat16* Ql = g_ql + (size_t)bh * TT * DD;
    const __nv_bfloat16* Kh = g_kh + (size_t)bh * TT * DD;
    const __nv_bfloat16* Kl = g_kl + (size_t)bh * TT * DD;
    const __nv_bfloat16* Vh = g_vh + (size_t)bh * TT * DD;
    const __nv_bfloat16* Vl = g_vl + (size_t)bh * TT * DD;
    const float* amp = am + b * TT;

    uint32_t qh[4][4], ql[4][4];
#pragma unroll
    for (int ks = 0; ks < 4; ks++) {
#pragma unroll
        for (int half = 0; half < 2; half++) {
            const int col = ks * 16 + half * 8 + c * 2;
            qh[ks][half * 2 + 0] = *(const uint32_t*)(Qh + (size_t)r1 * DD + col);
            qh[ks][half * 2 + 1] = *(const uint32_t*)(Qh + (size_t)r2 * DD + col);
            ql[ks][half * 2 + 0] = *(const uint32_t*)(Ql + (size_t)r1 * DD + col);
            ql[ks][half * 2 + 1] = *(const uint32_t*)(Ql + (size_t)r2 * DD + col);
        }
    }

    float o[8][4];
#pragma unroll
    for (int nt = 0; nt < 8; nt++)
#pragma unroll
        for (int i = 0; i < 4; i++) o[nt][i] = 0.0f;
    float m0v = -1e30f, m1v = -1e30f;
    float l0 = 0.0f, l1 = 0.0f;

    const int g4 = lane >> 3;
    const int l8 = lane & 7;

    const int nkv = 2 * (qtile + 1);
    attn_stage_load(sb0, Kh, Kl, Vh, Vl, amp, 0, tid);
    cp_commit();

    for (int kt = 0; kt < nkv; kt++) {
        const int k0 = kt * 64;
        cp_wait<0>();
        __syncthreads();

        const uint32_t st = sb0 + (kt & 1) * A_STAGE;
        const uint32_t skh = st, skl = st + A_BUF;
        const uint32_t svh = st + 2 * A_BUF, svl = st + 3 * A_BUF;
        const float* amS = (const float*)(dsm + (kt & 1) * A_STAGE + 4 * A_BUF);
        const bool needCausal = (kt >= 2 * qtile);

        if (kt + 1 < nkv)
            attn_stage_load(sb0 + ((kt + 1) & 1) * A_STAGE,
                            Kh, Kl, Vh, Vl, amp, (kt + 1) * 64, tid);
        cp_commit();

        float s[8][4];
#pragma unroll
        for (int nt = 0; nt < 8; nt++)
#pragma unroll
            for (int i = 0; i < 4; i++) s[nt][i] = 0.0f;

#pragma unroll
        for (int ks = 0; ks < 4; ks++) {
#pragma unroll
            for (int nt2 = 0; nt2 < 4; nt2++) {
                const uint32_t off =
                    ((nt2 * 16 + (g4 >> 1) * 8 + l8) * KVROW +
                     ks * 16 + (g4 & 1) * 8) * 2;
                uint32_t bhf[4], blf[4];
                ldmatrix_x4(bhf, skh + off);
                ldmatrix_x4(blf, skl + off);
                mma_bf16(s[nt2 * 2 + 0], qh[ks], bhf);
                mma_bf16(s[nt2 * 2 + 1], qh[ks], bhf + 2);
                mma_bf16(s[nt2 * 2 + 0], qh[ks], blf);
                mma_bf16(s[nt2 * 2 + 1], qh[ks], blf + 2);
                mma_bf16(s[nt2 * 2 + 0], ql[ks], bhf);
                mma_bf16(s[nt2 * 2 + 1], ql[ks], bhf + 2);
            }
        }

#pragma unroll
        for (int nt = 0; nt < 8; nt++) {
            const int colb = nt * 8 + c * 2;
            const float a0 = amS[colb] * NEGINF;
            const float a1 = amS[colb + 1] * NEGINF;
            s[nt][0] = s[nt][0] * 0.125f + a0;
            s[nt][1] = s[nt][1] * 0.125f + a1;
            s[nt][2] = s[nt][2] * 0.125f + a0;
            s[nt][3] = s[nt][3] * 0.125f + a1;
            if (needCausal) {
                const int kg0 = k0 + colb;
                if (kg0 > r1)     s[nt][0] = -1e30f;
                if (kg0 + 1 > r1) s[nt][1] = -1e30f;
                if (kg0 > r2)     s[nt][2] = -1e30f;
                if (kg0 + 1 > r2) s[nt][3] = -1e30f;
            }
        }

        float t0 = -1e30f, t1 = -1e30f;
#pragma unroll
        for (int nt = 0; nt < 8; nt++) {
            t0 = fmaxf(t0, fmaxf(s[nt][0], s[nt][1]));
            t1 = fmaxf(t1, fmaxf(s[nt][2], s[nt][3]));
        }
        t0 = fmaxf(t0, __shfl_xor_sync(0xffffffffu, t0, 1));
        t0 = fmaxf(t0, __shfl_xor_sync(0xffffffffu, t0, 2));
        t1 = fmaxf(t1, __shfl_xor_sync(0xffffffffu, t1, 1));
        t1 = fmaxf(t1, __shfl_xor_sync(0xffffffffu, t1, 2));

        const float mn0 = fmaxf(m0v, t0);
        const float mn1 = fmaxf(m1v, t1);
        const float cr0 = __expf(m0v - mn0);
        const float cr1 = __expf(m1v - mn1);
        m0v = mn0; m1v = mn1;

        float s0 = 0.0f, s1 = 0.0f;
#pragma unroll
        for (int nt = 0; nt < 8; nt++) {
            s[nt][0] = __expf(s[nt][0] - mn0);
            s[nt][1] = __expf(s[nt][1] - mn0);
            s[nt][2] = __expf(s[nt][2] - mn1);
            s[nt][3] = __expf(s[nt][3] - mn1);
            s0 += s[nt][0] + s[nt][1];
            s1 += s[nt][2] + s[nt][3];
            o[nt][0] *= cr0; o[nt][1] *= cr0;
            o[nt][2] *= cr1; o[nt][3] *= cr1;
        }
        s0 += __shfl_xor_sync(0xffffffffu, s0, 1);
        s0 += __shfl_xor_sync(0xffffffffu, s0, 2);
        s1 += __shfl_xor_sync(0xffffffffu, s1, 1);
        s1 += __shfl_xor_sync(0xffffffffu, s1, 2);
        l0 = l0 * cr0 + s0;
        l1 = l1 * cr1 + s1;

#pragma unroll
        for (int j = 0; j < 4; j++) {
            uint32_t pfh[4], pfl[4];
            {
                const float p00 = s[2 * j][0],     p01 = s[2 * j][1];
                const float p10 = s[2 * j][2],     p11 = s[2 * j][3];
                const float p20 = s[2 * j + 1][0], p21 = s[2 * j + 1][1];
                const float p30 = s[2 * j + 1][2], p31 = s[2 * j + 1][3];
                const float h00 = __bfloat162float(__float2bfloat16(p00));
                const float h01 = __bfloat162float(__float2bfloat16(p01));
                const float h10 = __bfloat162float(__float2bfloat16(p10));
                const float h11 = __bfloat162float(__float2bfloat16(p11));
                const float h20 = __bfloat162float(__float2bfloat16(p20));
                const float h21 = __bfloat162float(__float2bfloat16(p21));
                const float h30 = __bfloat162float(__float2bfloat16(p30));
                const float h31 = __bfloat162float(__float2bfloat16(p31));
                pfh[0] = pack_bf16(p00, p01);
                pfh[1] = pack_bf16(p10, p11);
                pfh[2] = pack_bf16(p20, p21);
                pfh[3] = pack_bf16(p30, p31);
                pfl[0] = pack_bf16(p00 - h00, p01 - h01);
                pfl[1] = pack_bf16(p10 - h10, p11 - h11);
                pfl[2] = pack_bf16(p20 - h20, p21 - h21);
                pfl[3] = pack_bf16(p30 - h30, p31 - h31);
            }
#pragma unroll
            for (int nt2 = 0; nt2 < 4; nt2++) {
                const uint32_t off =
                    ((16 * j + (g4 & 1) * 8 + l8) * KVROW +
                     nt2 * 16 + (g4 >> 1) * 8) * 2;
                uint32_t vhf[4], vlf[4];
                ldmatrix_x4_trans(vhf, svh + off);
                ldmatrix_x4_trans(vlf, svl + off);
                mma_bf16(o[nt2 * 2 + 0], pfh, vhf);
                mma_bf16(o[nt2 * 2 + 1], pfh, vhf + 2);
                mma_bf16(o[nt2 * 2 + 0], pfh, vlf);
                mma_bf16(o[nt2 * 2 + 1], pfh, vlf + 2);
                mma_bf16(o[nt2 * 2 + 0], pfl, vhf);
                mma_bf16(o[nt2 * 2 + 1], pfl, vhf + 2);
            }
        }
    }

    const float i0 = 1.0f / l0;
    const float i1 = 1.0f / l1;
    __nv_bfloat16* Yh1 = g_yh + (size_t)(b * TT + r1) * CC + h * DD;
    __nv_bfloat16* Yl1 = g_yl + (size_t)(b * TT + r1) * CC + h * DD;
    __nv_bfloat16* Yh2 = g_yh + (size_t)(b * TT + r2) * CC + h * DD;
    __nv_bfloat16* Yl2 = g_yl + (size_t)(b * TT + r2) * CC + h * DD;
#pragma unroll
    for (int nt = 0; nt < 8; nt++) {
        const int col = nt * 8 + c * 2;
        const float w0x = o[nt][0] * i0, w0y = o[nt][1] * i0;
        const float w1x = o[nt][2] * i1, w1y = o[nt][3] * i1;
        const float h0x = __bfloat162float(__float2bfloat16(w0x));
        const float h0y = __bfloat162float(__float2bfloat16(w0y));
        const float h1x = __bfloat162float(__float2bfloat16(w1x));
        const float h1y = __bfloat162float(__float2bfloat16(w1y));
        *(uint32_t*)(Yh1 + col) = pack_bf16(w0x, w0y);
        *(uint32_t*)(Yl1 + col) = pack_bf16(w0x - h0x, w0y - h0y);
        *(uint32_t*)(Yh2 + col) = pack_bf16(w1x, w1y);
        *(uint32_t*)(Yl2 + col) = pack_bf16(w1x - h1x, w1y - h1y);
    }
}

// ---------------------------------------------------------------------------
extern "C" void kernel_launch(void* const* d_in, const int* in_sizes, int n_in,
                              void* d_out, int out_size)
{
    (void)in_sizes; (void)n_in; (void)out_size;
    const float* x  = (const float*)d_in[0];   // [B,T,C]
    const float* am = (const float*)d_in[1];   // [B,T]
    const float* Wa = (const float*)d_in[2];   // [C,3C]
    const float* ba = (const float*)d_in[3];   // [3C]
    const float* Wp = (const float*)d_in[4];   // [C,C]
    const float* bp = (const float*)d_in[5];   // [C]
    float* out = (float*)d_out;                // [B,T,C]

    cudaFuncSetAttribute(tc_gemm_kernel,
                         cudaFuncAttributeMaxDynamicSharedMemorySize, GEMM_SMEM);
    cudaFuncSetAttribute(attn_tc_kernel,
                         cudaFuncAttributeMaxDynamicSharedMemorySize, ATTN_SMEM);

    __nv_bfloat16 *xh, *xl, *yh, *yl, *wah, *wal, *wph, *wpl;
    cudaGetSymbolAddress((void**)&xh,  g_xh);
    cudaGetSymbolAddress((void**)&xl,  g_xl);
    cudaGetSymbolAddress((void**)&yh,  g_yh);
    cudaGetSymbolAddress((void**)&yl,  g_yl);
    cudaGetSymbolAddress((void**)&wah, g_wah);
    cudaGetSymbolAddress((void**)&wal, g_wal);
    cudaGetSymbolAddress((void**)&wph, g_wph);
    cudaGetSymbolAddress((void**)&wpl, g_wpl);

    const int M = BB * TT;          // 4096

    split_kernel<<<(M * CC) / 256, 256>>>(x, xh, xl, M * CC);
    transpose_split_kernel<<<dim3(3 * CC / 32, CC / 32), dim3(32, 8)>>>(
        Wa, wah, wal, CC, 3 * CC);
    transpose_split_kernel<<<dim3(CC / 32, CC / 32), dim3(32, 8)>>>(
        Wp, wph, wpl, CC, CC);

    tc_gemm_kernel<<<dim3(3 * CC / 128, M / 128), 256, GEMM_SMEM>>>(
        xh, xl, wah, wal, ba, nullptr, 3 * CC, 0);

    attn_tc_kernel<<<dim3(TT / 128, BB * HH), 256, ATTN_SMEM>>>(am);

    tc_gemm_kernel<<<dim3(CC / 128, M / 128), 256, GEMM_SMEM>>>(
        yh, yl, wph, wpl, bp, out, CC, 1);
}

// round 11
// speedup vs baseline: 1.2295x; 1.2295x over previous
#include <cuda_runtime.h>
#include <cuda_bf16.h>
#include <cstdint>
#include <cstddef>

// Problem constants
#define BB 2
#define TT 2048
#define CC 1024
#define HH 16
#define DD 64
#define NEGINF (-1e10f)

// ---------------------------------------------------------------------------
// Device-global scratch (no allocation allowed). q/k/v/y live ONLY as
// pre-split bf16 hi/lo pairs.
// ---------------------------------------------------------------------------
__device__ __nv_bfloat16 g_qh[(size_t)BB * HH * TT * DD];
__device__ __nv_bfloat16 g_ql[(size_t)BB * HH * TT * DD];
__device__ __nv_bfloat16 g_kh[(size_t)BB * HH * TT * DD];
__device__ __nv_bfloat16 g_kl[(size_t)BB * HH * TT * DD];
__device__ __nv_bfloat16 g_vh[(size_t)BB * HH * TT * DD];
__device__ __nv_bfloat16 g_vl[(size_t)BB * HH * TT * DD];
__device__ __nv_bfloat16 g_yh[(size_t)BB * TT * CC];
__device__ __nv_bfloat16 g_yl[(size_t)BB * TT * CC];

__device__ __nv_bfloat16 g_xh[(size_t)BB * TT * CC];
__device__ __nv_bfloat16 g_xl[(size_t)BB * TT * CC];
__device__ __nv_bfloat16 g_wah[(size_t)3 * CC * CC];
__device__ __nv_bfloat16 g_wal[(size_t)3 * CC * CC];
__device__ __nv_bfloat16 g_wph[(size_t)CC * CC];
__device__ __nv_bfloat16 g_wpl[(size_t)CC * CC];

// ---------------------------------------------------------------------------
// PTX helpers (sm_80+ — legal on plain sm_100 target)
// ---------------------------------------------------------------------------
__device__ __forceinline__ uint32_t smem_u32(const void* p) {
    return (uint32_t)__cvta_generic_to_shared(p);
}
__device__ __forceinline__ void cp16(uint32_t s, const void* g) {
    asm volatile("cp.async.cg.shared.global [%0], [%1], 16;" :: "r"(s), "l"(g));
}
__device__ __forceinline__ void cp_commit() {
    asm volatile("cp.async.commit_group;" ::: "memory");
}
template <int N>
__device__ __forceinline__ void cp_wait() {
    asm volatile("cp.async.wait_group %0;" :: "n"(N) : "memory");
}
__device__ __forceinline__ void ldmatrix_x4(uint32_t* r, uint32_t addr) {
    asm volatile("ldmatrix.sync.aligned.m8n8.x4.shared.b16 {%0,%1,%2,%3}, [%4];"
                 : "=r"(r[0]), "=r"(r[1]), "=r"(r[2]), "=r"(r[3]) : "r"(addr));
}
__device__ __forceinline__ void ldmatrix_x4_trans(uint32_t* r, uint32_t addr) {
    asm volatile("ldmatrix.sync.aligned.m8n8.x4.trans.shared.b16 {%0,%1,%2,%3}, [%4];"
                 : "=r"(r[0]), "=r"(r[1]), "=r"(r[2]), "=r"(r[3]) : "r"(addr));
}
__device__ __forceinline__ void mma_bf16(float* d, const uint32_t* a,
                                         const uint32_t* b) {
    asm volatile(
        "mma.sync.aligned.m16n8k16.row.col.f32.bf16.bf16.f32 "
        "{%0,%1,%2,%3}, {%4,%5,%6,%7}, {%8,%9}, {%0,%1,%2,%3};"
        : "+f"(d[0]), "+f"(d[1]), "+f"(d[2]), "+f"(d[3])
        : "r"(a[0]), "r"(a[1]), "r"(a[2]), "r"(a[3]), "r"(b[0]), "r"(b[1]));
}
// pack two f32 as bf16x2: first arg -> low half
__device__ __forceinline__ uint32_t pack_bf16(float lo, float hi) {
    uint32_t r;
    asm("cvt.rn.bf16x2.f32 %0, %1, %2;" : "=r"(r) : "f"(hi), "f"(lo));
    return r;
}

// ---------------------------------------------------------------------------
// Convert kernels: fp32 -> (bf16 hi, bf16 lo)
// ---------------------------------------------------------------------------
__global__ void split_kernel(const float* __restrict__ src,
                             __nv_bfloat16* __restrict__ hi,
                             __nv_bfloat16* __restrict__ lo, int n)
{
    int i = blockIdx.x * blockDim.x + threadIdx.x;
    if (i < n) {
        float v = src[i];
        __nv_bfloat16 h = __float2bfloat16(v);
        hi[i] = h;
        lo[i] = __float2bfloat16(v - __bfloat162float(h));
    }
}

__global__ void transpose_split_kernel(const float* __restrict__ src,
                                       __nv_bfloat16* __restrict__ hi,
                                       __nv_bfloat16* __restrict__ lo,
                                       int K, int N)
{
    __shared__ float tile[32][33];
    const int k0 = blockIdx.y * 32;
    const int n0 = blockIdx.x * 32;
    const int tx = threadIdx.x, ty = threadIdx.y;  // (32, 8)
#pragma unroll
    for (int i = ty; i < 32; i += 8)
        tile[i][tx] = src[(size_t)(k0 + i) * N + n0 + tx];
    __syncthreads();
#pragma unroll
    for (int i = ty; i < 32; i += 8) {
        float v = tile[tx][i];
        __nv_bfloat16 h = __float2bfloat16(v);
        size_t o = (size_t)(n0 + i) * K + k0 + tx;
        hi[o] = h;
        lo[o] = __float2bfloat16(v - __bfloat162float(h));
    }
}

// ---------------------------------------------------------------------------
// cp.async double-buffered mma.sync bf16 3-pass GEMM (R7 layout/pipeline).
// CTA tile 128x128, BK=32. 4 warps (128 threads) in 2x2 grid, 64x64/warp
// -> smem bytes per MMA drops 128B -> 83B (crossbar no longer binding).
// ---------------------------------------------------------------------------
#define BK 32
#define LDS_ROW 40                 // 80B rows, 16B-aligned, conflict-free
#define G_BUF 10240                // 128*40*2
#define G_STAGE (4 * G_BUF)        // 40960
#define GEMM_SMEM (2 * G_STAGE)    // 81920

// 128 threads; sub in 0..3 covers all 128 rows x 32 cols of 4 buffers.
__device__ __forceinline__ void gemm_stage_load(
    uint32_t sb,
    const __nv_bfloat16* Ahi, const __nv_bfloat16* Alo,
    const __nv_bfloat16* Bhi, const __nv_bfloat16* Blo,
    int m0, int n0, int k0, int tid, int sub)
{
    const int K = CC;
    const int idx = sub * 128 + tid;   // 0..511
    const int r = idx >> 2;
    const int c = (idx & 3) * 8;
    const uint32_t so = (uint32_t)(r * LDS_ROW + c) * 2;
    const size_t goA = (size_t)(m0 + r) * K + k0 + c;
    const size_t goB = (size_t)(n0 + r) * K + k0 + c;
    cp16(sb + 0 * G_BUF + so, Ahi + goA);
    cp16(sb + 1 * G_BUF + so, Alo + goA);
    cp16(sb + 2 * G_BUF + so, Bhi + goB);
    cp16(sb + 3 * G_BUF + so, Blo + goB);
}

__global__ __launch_bounds__(128, 2) void tc_gemm_kernel(
    const __nv_bfloat16* __restrict__ Ahi, const __nv_bfloat16* __restrict__ Alo,
    const __nv_bfloat16* __restrict__ Bhi, const __nv_bfloat16* __restrict__ Blo,
    const float* __restrict__ bias, float* __restrict__ Cout,
    int N, int mode)
{
    extern __shared__ __align__(16) char dsm[];
    const uint32_t sb0 = smem_u32(dsm);

    const int tid = threadIdx.x;
    const int warp = tid >> 5;
    const int lane = tid & 31;
    const int warpM = warp >> 1;        // 0..1 (64 rows each)
    const int warpN = warp & 1;         // 0..1 (64 cols each)
    const int m0 = blockIdx.y * 128;
    const int n0 = blockIdx.x * 128;

    float acc[4][8][4];                 // mt x nt x frag
#pragma unroll
    for (int mt = 0; mt < 4; mt++)
#pragma unroll
        for (int nt = 0; nt < 8; nt++)
#pragma unroll
            for (int i = 0; i < 4; i++) acc[mt][nt][i] = 0.0f;

    const int aRow = warpM * 64 + (lane & 15);
    const int aK   = (lane >> 4) * 8;
    // B ldmatrix.x4: covers 16 output cols per instr (two 8-col n-tiles)
    const int bRow4 = warpN * 64 + (lane >> 4) * 8 + (lane & 7);
    const int bK4   = ((lane >> 3) & 1) * 8;

    const int NCH = CC / BK;   // 32

    gemm_stage_load(sb0, Ahi, Alo, Bhi, Blo, m0, n0, 0, tid, 0);
    gemm_stage_load(sb0, Ahi, Alo, Bhi, Blo, m0, n0, 0, tid, 1);
    gemm_stage_load(sb0, Ahi, Alo, Bhi, Blo, m0, n0, 0, tid, 2);
    gemm_stage_load(sb0, Ahi, Alo, Bhi, Blo, m0, n0, 0, tid, 3);
    cp_commit();

    for (int ch = 0; ch < NCH; ch++) {
        cp_wait<0>();
        __syncthreads();

        const uint32_t st = sb0 + (ch & 1) * G_STAGE;
        const uint32_t sa_hi = st, sa_lo = st + G_BUF;
        const uint32_t sb_hi = st + 2 * G_BUF, sb_lo = st + 3 * G_BUF;
        const bool pf = (ch + 1 < NCH);
        const uint32_t pb = sb0 + ((ch + 1) & 1) * G_STAGE;

        // first half of next-chunk prefetch (R7 placement)
        if (pf) {
            gemm_stage_load(pb, Ahi, Alo, Bhi, Blo, m0, n0, (ch + 1) * BK, tid, 0);
            gemm_stage_load(pb, Ahi, Alo, Bhi, Blo, m0, n0, (ch + 1) * BK, tid, 1);
        }

#pragma unroll
        for (int ks = 0; ks < 2; ks++) {
            const int kk = ks * 16;
            uint32_t afh[4][4], afl[4][4], bfh[4][4], bfl[4][4];
#pragma unroll
            for (int mt = 0; mt < 4; mt++) {
                const uint32_t off = ((aRow + mt * 16) * LDS_ROW + aK + kk) * 2;
                ldmatrix_x4(afh[mt], sa_hi + off);
                ldmatrix_x4(afl[mt], sa_lo + off);
            }
#pragma unroll
            for (int bp = 0; bp < 4; bp++) {
                const uint32_t off = ((bRow4 + bp * 16) * LDS_ROW + bK4 + kk) * 2;
                ldmatrix_x4(bfh[bp], sb_hi + off);
                ldmatrix_x4(bfl[bp], sb_lo + off);
            }
#pragma unroll
            for (int mt = 0; mt < 4; mt++)
#pragma unroll
                for (int nt = 0; nt < 8; nt++) {
                    const uint32_t* bh = bfh[nt >> 1] + (nt & 1) * 2;
                    const uint32_t* bl = bfl[nt >> 1] + (nt & 1) * 2;
                    mma_bf16(acc[mt][nt], afh[mt], bh);
                    mma_bf16(acc[mt][nt], afh[mt], bl);
                    mma_bf16(acc[mt][nt], afl[mt], bh);
                }
            if (ks == 0) {
                if (pf) {
                    gemm_stage_load(pb, Ahi, Alo, Bhi, Blo, m0, n0,
                                    (ch + 1) * BK, tid, 2);
                    gemm_stage_load(pb, Ahi, Alo, Bhi, Blo, m0, n0,
                                    (ch + 1) * BK, tid, 3);
                }
                cp_commit();
            }
        }
    }

    // epilogue
#pragma unroll
    for (int mt = 0; mt < 4; mt++) {
#pragma unroll
        for (int i = 0; i < 2; i++) {
            const int m = m0 + warpM * 64 + mt * 16 + (lane >> 2) + i * 8;
            const int b = m >> 11;
            const int t = m & 2047;
#pragma unroll
            for (int nt = 0; nt < 8; nt++) {
                const int n = n0 + warpN * 64 + nt * 8 + (lane & 3) * 2;
                const float v0 = acc[mt][nt][i * 2 + 0] + bias[n];
                const float v1 = acc[mt][nt][i * 2 + 1] + bias[n + 1];
                if (mode == 0) {
                    const int region = n >> 10;      // 0=q 1=k 2=v
                    const int cc = n & 1023;
                    const int h = cc >> 6;
                    const int dd = cc & 63;
                    __nv_bfloat16* dh = (region == 0) ? g_qh
                                      : (region == 1) ? g_kh : g_vh;
                    __nv_bfloat16* dl = (region == 0) ? g_ql
                                      : (region == 1) ? g_kl : g_vl;
                    const size_t o = (((size_t)b * HH + h) * TT + t) * DD + dd;
                    const float h0 = __bfloat162float(__float2bfloat16(v0));
                    const float h1 = __bfloat162float(__float2bfloat16(v1));
                    *(uint32_t*)(dh + o) = pack_bf16(v0, v1);
                    *(uint32_t*)(dl + o) = pack_bf16(v0 - h0, v1 - h1);
                } else {
                    float2 w; w.x = v0; w.y = v1;
                    *(float2*)(Cout + (size_t)m * N + n) = w;
                }
            }
        }
    }
}

// ---------------------------------------------------------------------------
// cp.async double-buffered tensor-core flash attention (hi/lo compensated).
// Exact Round-7 version (passing, rel_err 1.66e-5).
// ---------------------------------------------------------------------------
#define KVROW 72
#define A_BUF (64 * KVROW * 2)
#define A_STAGE (4 * A_BUF + 256)
#define ATTN_SMEM (2 * A_STAGE)

__device__ __forceinline__ void attn_stage_load(
    uint32_t sb,
    const __nv_bfloat16* Kh, const __nv_bfloat16* Kl,
    const __nv_bfloat16* Vh, const __nv_bfloat16* Vl,
    const float* amp, int k0, int tid)
{
    const int r = tid >> 2;
    const int s2 = (tid & 3) * 2;
#pragma unroll
    for (int i = 0; i < 2; i++) {
        const int seg = s2 + i;
        const uint32_t so = (uint32_t)(r * KVROW + seg * 8) * 2;
        const size_t go = (size_t)(k0 + r) * DD + seg * 8;
        cp16(sb + 0 * A_BUF + so, Kh + go);
        cp16(sb + 1 * A_BUF + so, Kl + go);
        cp16(sb + 2 * A_BUF + so, Vh + go);
        cp16(sb + 3 * A_BUF + so, Vl + go);
    }
    if (tid < 16) cp16(sb + 4 * A_BUF + tid * 16, amp + k0 + tid * 4);
}

__global__ __launch_bounds__(256) void attn_tc_kernel(const float* __restrict__ am)
{
    extern __shared__ __align__(16) char dsm[];
    const uint32_t sb0 = smem_u32(dsm);

    const int tid = threadIdx.x;
    const int warp = tid >> 5;
    const int lane = tid & 31;
    const int g = lane >> 2;
    const int c = lane & 3;
    const int bh = blockIdx.y;
    const int b = bh >> 4;
    const int h = bh & 15;
    const int qtile = gridDim.x - 1 - blockIdx.x;
    const int q0 = qtile * 128;

    const int r1 = q0 + warp * 16 + g;
    const int r2 = r1 + 8;

    const __nv_bfloat16* Qh = g_qh + (size_t)bh * TT * DD;
    const __nv_bfloat16* Ql = g_ql + (size_t)bh * TT * DD;
    const __nv_bfloat16* Kh = g_kh + (size_t)bh * TT * DD;
    const __nv_bfloat16* Kl = g_kl + (size_t)bh * TT * DD;
    const __nv_bfloat16* Vh = g_vh + (size_t)bh * TT * DD;
    const __nv_bfloat16* Vl = g_vl + (size_t)bh * TT * DD;
    const float* amp = am + b * TT;

    uint32_t qh[4][4], ql[4][4];
#pragma unroll
    for (int ks = 0; ks < 4; ks++) {
#pragma unroll
        for (int half = 0; half < 2; half++) {
            const int col = ks * 16 + half * 8 + c * 2;
            qh[ks][half * 2 + 0] = *(const uint32_t*)(Qh + (size_t)r1 * DD + col);
            qh[ks][half * 2 + 1] = *(const uint32_t*)(Qh + (size_t)r2 * DD + col);
            ql[ks][half * 2 + 0] = *(const uint32_t*)(Ql + (size_t)r1 * DD + col);
            ql[ks][half * 2 + 1] = *(const uint32_t*)(Ql + (size_t)r2 * DD + col);
        }
    }

    float o[8][4];
#pragma unroll
    for (int nt = 0; nt < 8; nt++)
#pragma unroll
        for (int i = 0; i < 4; i++) o[nt][i] = 0.0f;
    float m0v = -1e30f, m1v = -1e30f;
    float l0 = 0.0f, l1 = 0.0f;

    const int g4 = lane >> 3;
    const int l8 = lane & 7;

    const int nkv = 2 * (qtile + 1);
    attn_stage_load(sb0, Kh, Kl, Vh, Vl, amp, 0, tid);
    cp_commit();

    for (int kt = 0; kt < nkv; kt++) {
        const int k0 = kt * 64;
        cp_wait<0>();
        __syncthreads();

        const uint32_t st = sb0 + (kt & 1) * A_STAGE;
        const uint32_t skh = st, skl = st + A_BUF;
        const uint32_t svh = st + 2 * A_BUF, svl = st + 3 * A_BUF;
        const float* amS = (const float*)(dsm + (kt & 1) * A_STAGE + 4 * A_BUF);
        const bool needCausal = (kt >= 2 * qtile);

        if (kt + 1 < nkv)
            attn_stage_load(sb0 + ((kt + 1) & 1) * A_STAGE,
                            Kh, Kl, Vh, Vl, amp, (kt + 1) * 64, tid);
        cp_commit();

        float s[8][4];
#pragma unroll
        for (int nt = 0; nt < 8; nt++)
#pragma unroll
            for (int i = 0; i < 4; i++) s[nt][i] = 0.0f;

#pragma unroll
        for (int ks = 0; ks < 4; ks++) {
#pragma unroll
            for (int nt2 = 0; nt2 < 4; nt2++) {
                const uint32_t off =
                    ((nt2 * 16 + (g4 >> 1) * 8 + l8) * KVROW +
                     ks * 16 + (g4 & 1) * 8) * 2;
                uint32_t bhf[4], blf[4];
                ldmatrix_x4(bhf, skh + off);
                ldmatrix_x4(blf, skl + off);
                mma_bf16(s[nt2 * 2 + 0], qh[ks], bhf);
                mma_bf16(s[nt2 * 2 + 1], qh[ks], bhf + 2);
                mma_bf16(s[nt2 * 2 + 0], qh[ks], blf);
                mma_bf16(s[nt2 * 2 + 1], qh[ks], blf + 2);
                mma_bf16(s[nt2 * 2 + 0], ql[ks], bhf);
                mma_bf16(s[nt2 * 2 + 1], ql[ks], bhf + 2);
            }
        }

#pragma unroll
        for (int nt = 0; nt < 8; nt++) {
            const int colb = nt * 8 + c * 2;
            const float a0 = amS[colb] * NEGINF;
            const float a1 = amS[colb + 1] * NEGINF;
            s[nt][0] = s[nt][0] * 0.125f + a0;
            s[nt][1] = s[nt][1] * 0.125f + a1;
            s[nt][2] = s[nt][2] * 0.125f + a0;
            s[nt][3] = s[nt][3] * 0.125f + a1;
            if (needCausal) {
                const int kg0 = k0 + colb;
                if (kg0 > r1)     s[nt][0] = -1e30f;
                if (kg0 + 1 > r1) s[nt][1] = -1e30f;
                if (kg0 > r2)     s[nt][2] = -1e30f;
                if (kg0 + 1 > r2) s[nt][3] = -1e30f;
            }
        }

        float t0 = -1e30f, t1 = -1e30f;
#pragma unroll
        for (int nt = 0; nt < 8; nt++) {
            t0 = fmaxf(t0, fmaxf(s[nt][0], s[nt][1]));
            t1 = fmaxf(t1, fmaxf(s[nt][2], s[nt][3]));
        }
        t0 = fmaxf(t0, __shfl_xor_sync(0xffffffffu, t0, 1));
        t0 = fmaxf(t0, __shfl_xor_sync(0xffffffffu, t0, 2));
        t1 = fmaxf(t1, __shfl_xor_sync(0xffffffffu, t1, 1));
        t1 = fmaxf(t1, __shfl_xor_sync(0xffffffffu, t1, 2));

        const float mn0 = fmaxf(m0v, t0);
        const float mn1 = fmaxf(m1v, t1);
        const float cr0 = __expf(m0v - mn0);
        const float cr1 = __expf(m1v - mn1);
        m0v = mn0; m1v = mn1;

        float s0 = 0.0f, s1 = 0.0f;
#pragma unroll
        for (int nt = 0; nt < 8; nt++) {
            s[nt][0] = __expf(s[nt][0] - mn0);
            s[nt][1] = __expf(s[nt][1] - mn0);
            s[nt][2] = __expf(s[nt][2] - mn1);
            s[nt][3] = __expf(s[nt][3] - mn1);
            s0 += s[nt][0] + s[nt][1];
            s1 += s[nt][2] + s[nt][3];
            o[nt][0] *= cr0; o[nt][1] *= cr0;
            o[nt][2] *= cr1; o[nt][3] *= cr1;
        }
        s0 += __shfl_xor_sync(0xffffffffu, s0, 1);
        s0 += __shfl_xor_sync(0xffffffffu, s0, 2);
        s1 += __shfl_xor_sync(0xffffffffu, s1, 1);
        s1 += __shfl_xor_sync(0xffffffffu, s1, 2);
        l0 = l0 * cr0 + s0;
        l1 = l1 * cr1 + s1;

#pragma unroll
        for (int j = 0; j < 4; j++) {
            uint32_t pfh[4], pfl[4];
            {
                const float p00 = s[2 * j][0],     p01 = s[2 * j][1];
                const float p10 = s[2 * j][2],     p11 = s[2 * j][3];
                const float p20 = s[2 * j + 1][0], p21 = s[2 * j + 1][1];
                const float p30 = s[2 * j + 1][2], p31 = s[2 * j + 1][3];
                const float h00 = __bfloat162float(__float2bfloat16(p00));
                const float h01 = __bfloat162float(__float2bfloat16(p01));
                const float h10 = __bfloat162float(__float2bfloat16(p10));
                const float h11 = __bfloat162float(__float2bfloat16(p11));
                const float h20 = __bfloat162float(__float2bfloat16(p20));
                const float h21 = __bfloat162float(__float2bfloat16(p21));
                const float h30 = __bfloat162float(__float2bfloat16(p30));
                const float h31 = __bfloat162float(__float2bfloat16(p31));
                pfh[0] = pack_bf16(p00, p01);
                pfh[1] = pack_bf16(p10, p11);
                pfh[2] = pack_bf16(p20, p21);
                pfh[3] = pack_bf16(p30, p31);
                pfl[0] = pack_bf16(p00 - h00, p01 - h01);
                pfl[1] = pack_bf16(p10 - h10, p11 - h11);
                pfl[2] = pack_bf16(p20 - h20, p21 - h21);
                pfl[3] = pack_bf16(p30 - h30, p31 - h31);
            }
#pragma unroll
            for (int nt2 = 0; nt2 < 4; nt2++) {
                const uint32_t off =
                    ((16 * j + (g4 & 1) * 8 + l8) * KVROW +
                     nt2 * 16 + (g4 >> 1) * 8) * 2;
                uint32_t vhf[4], vlf[4];
                ldmatrix_x4_trans(vhf, svh + off);
                ldmatrix_x4_trans(vlf, svl + off);
                mma_bf16(o[nt2 * 2 + 0], pfh, vhf);
                mma_bf16(o[nt2 * 2 + 1], pfh, vhf + 2);
                mma_bf16(o[nt2 * 2 + 0], pfh, vlf);
                mma_bf16(o[nt2 * 2 + 1], pfh, vlf + 2);
                mma_bf16(o[nt2 * 2 + 0], pfl, vhf);
                mma_bf16(o[nt2 * 2 + 1], pfl, vhf + 2);
            }
        }
    }

    const float i0 = 1.0f / l0;
    const float i1 = 1.0f / l1;
    __nv_bfloat16* Yh1 = g_yh + (size_t)(b * TT + r1) * CC + h * DD;
    __nv_bfloat16* Yl1 = g_yl + (size_t)(b * TT + r1) * CC + h * DD;
    __nv_bfloat16* Yh2 = g_yh + (size_t)(b * TT + r2) * CC + h * DD;
    __nv_bfloat16* Yl2 = g_yl + (size_t)(b * TT + r2) * CC + h * DD;
#pragma unroll
    for (int nt = 0; nt < 8; nt++) {
        const int col = nt * 8 + c * 2;
        const float w0x = o[nt][0] * i0, w0y = o[nt][1] * i0;
        const float w1x = o[nt][2] * i1, w1y = o[nt][3] * i1;
        const float h0x = __bfloat162float(__float2bfloat16(w0x));
        const float h0y = __bfloat162float(__float2bfloat16(w0y));
        const float h1x = __bfloat162float(__float2bfloat16(w1x));
        const float h1y = __bfloat162float(__float2bfloat16(w1y));
        *(uint32_t*)(Yh1 + col) = pack_bf16(w0x, w0y);
        *(uint32_t*)(Yl1 + col) = pack_bf16(w0x - h0x, w0y - h0y);
        *(uint32_t*)(Yh2 + col) = pack_bf16(w1x, w1y);
        *(uint32_t*)(Yl2 + col) = pack_bf16(w1x - h1x, w1y - h1y);
    }
}

// ---------------------------------------------------------------------------
extern "C" void kernel_launch(void* const* d_in, const int* in_sizes, int n_in,
                              void* d_out, int out_size)
{
    (void)in_sizes; (void)n_in; (void)out_size;
    const float* x  = (const float*)d_in[0];   // [B,T,C]
    const float* am = (const float*)d_in[1];   // [B,T]
    const float* Wa = (const float*)d_in[2];   // [C,3C]
    const float* ba = (const float*)d_in[3];   // [3C]
    const float* Wp = (const float*)d_in[4];   // [C,C]
    const float* bp = (const float*)d_in[5];   // [C]
    float* out = (float*)d_out;                // [B,T,C]

    cudaFuncSetAttribute(tc_gemm_kernel,
                         cudaFuncAttributeMaxDynamicSharedMemorySize, GEMM_SMEM);
    cudaFuncSetAttribute(attn_tc_kernel,
                         cudaFuncAttributeMaxDynamicSharedMemorySize, ATTN_SMEM);

    __nv_bfloat16 *xh, *xl, *yh, *yl, *wah, *wal, *wph, *wpl;
    cudaGetSymbolAddress((void**)&xh,  g_xh);
    cudaGetSymbolAddress((void**)&xl,  g_xl);
    cudaGetSymbolAddress((void**)&yh,  g_yh);
    cudaGetSymbolAddress((void**)&yl,  g_yl);
    cudaGetSymbolAddress((void**)&wah, g_wah);
    cudaGetSymbolAddress((void**)&wal, g_wal);
    cudaGetSymbolAddress((void**)&wph, g_wph);
    cudaGetSymbolAddress((void**)&wpl, g_wpl);

    const int M = BB * TT;          // 4096

    split_kernel<<<(M * CC) / 256, 256>>>(x, xh, xl, M * CC);
    transpose_split_kernel<<<dim3(3 * CC / 32, CC / 32), dim3(32, 8)>>>(
        Wa, wah, wal, CC, 3 * CC);
    transpose_split_kernel<<<dim3(CC / 32, CC / 32), dim3(32, 8)>>>(
        Wp, wph, wpl, CC, CC);

    tc_gemm_kernel<<<dim3(3 * CC / 128, M / 128), 128, GEMM_SMEM>>>(
        xh, xl, wah, wal, ba, nullptr, 3 * CC, 0);

    attn_tc_kernel<<<dim3(TT / 128, BB * HH), 256, ATTN_SMEM>>>(am);

    tc_gemm_kernel<<<dim3(CC / 128, M / 128), 128, GEMM_SMEM>>>(
        yh, yl, wph, wpl, bp, out, CC, 1);
}

// round 13
// speedup vs baseline: 1.2344x; 1.0040x over previous
#include <cuda_runtime.h>
#include <cuda_bf16.h>
#include <cstdint>
#include <cstddef>

// Problem constants
#define BB 2
#define TT 2048
#define CC 1024
#define HH 16
#define DD 64
#define NEGINF (-1e10f)

// ---------------------------------------------------------------------------
// Device-global scratch (no allocation allowed). q/k/v/y live ONLY as
// pre-split bf16 hi/lo pairs.
// ---------------------------------------------------------------------------
__device__ __nv_bfloat16 g_qh[(size_t)BB * HH * TT * DD];
__device__ __nv_bfloat16 g_ql[(size_t)BB * HH * TT * DD];
__device__ __nv_bfloat16 g_kh[(size_t)BB * HH * TT * DD];
__device__ __nv_bfloat16 g_kl[(size_t)BB * HH * TT * DD];
__device__ __nv_bfloat16 g_vh[(size_t)BB * HH * TT * DD];
__device__ __nv_bfloat16 g_vl[(size_t)BB * HH * TT * DD];
__device__ __nv_bfloat16 g_yh[(size_t)BB * TT * CC];
__device__ __nv_bfloat16 g_yl[(size_t)BB * TT * CC];

__device__ __nv_bfloat16 g_xh[(size_t)BB * TT * CC];
__device__ __nv_bfloat16 g_xl[(size_t)BB * TT * CC];
__device__ __nv_bfloat16 g_wah[(size_t)3 * CC * CC];
__device__ __nv_bfloat16 g_wal[(size_t)3 * CC * CC];
__device__ __nv_bfloat16 g_wph[(size_t)CC * CC];
__device__ __nv_bfloat16 g_wpl[(size_t)CC * CC];

// ---------------------------------------------------------------------------
// PTX helpers (sm_80+ — legal on plain sm_100 target)
// ---------------------------------------------------------------------------
__device__ __forceinline__ uint32_t smem_u32(const void* p) {
    return (uint32_t)__cvta_generic_to_shared(p);
}
__device__ __forceinline__ void cp16(uint32_t s, const void* g) {
    asm volatile("cp.async.cg.shared.global [%0], [%1], 16;" :: "r"(s), "l"(g));
}
__device__ __forceinline__ void cp_commit() {
    asm volatile("cp.async.commit_group;" ::: "memory");
}
template <int N>
__device__ __forceinline__ void cp_wait() {
    asm volatile("cp.async.wait_group %0;" :: "n"(N) : "memory");
}
__device__ __forceinline__ void ldmatrix_x4(uint32_t* r, uint32_t addr) {
    asm volatile("ldmatrix.sync.aligned.m8n8.x4.shared.b16 {%0,%1,%2,%3}, [%4];"
                 : "=r"(r[0]), "=r"(r[1]), "=r"(r[2]), "=r"(r[3]) : "r"(addr));
}
__device__ __forceinline__ void ldmatrix_x4_trans(uint32_t* r, uint32_t addr) {
    asm volatile("ldmatrix.sync.aligned.m8n8.x4.trans.shared.b16 {%0,%1,%2,%3}, [%4];"
                 : "=r"(r[0]), "=r"(r[1]), "=r"(r[2]), "=r"(r[3]) : "r"(addr));
}
__device__ __forceinline__ void mma_bf16(float* d, const uint32_t* a,
                                         const uint32_t* b) {
    asm volatile(
        "mma.sync.aligned.m16n8k16.row.col.f32.bf16.bf16.f32 "
        "{%0,%1,%2,%3}, {%4,%5,%6,%7}, {%8,%9}, {%0,%1,%2,%3};"
        : "+f"(d[0]), "+f"(d[1]), "+f"(d[2]), "+f"(d[3])
        : "r"(a[0]), "r"(a[1]), "r"(a[2]), "r"(a[3]), "r"(b[0]), "r"(b[1]));
}
// pack two f32 as bf16x2: first arg -> low half
__device__ __forceinline__ uint32_t pack_bf16(float lo, float hi) {
    uint32_t r;
    asm("cvt.rn.bf16x2.f32 %0, %1, %2;" : "=r"(r) : "f"(hi), "f"(lo));
    return r;
}

// ---------------------------------------------------------------------------
// Convert kernels: fp32 -> (bf16 hi, bf16 lo)
// ---------------------------------------------------------------------------
__global__ void split_kernel(const float* __restrict__ src,
                             __nv_bfloat16* __restrict__ hi,
                             __nv_bfloat16* __restrict__ lo, int n)
{
    int i = blockIdx.x * blockDim.x + threadIdx.x;
    if (i < n) {
        float v = src[i];
        __nv_bfloat16 h = __float2bfloat16(v);
        hi[i] = h;
        lo[i] = __float2bfloat16(v - __bfloat162float(h));
    }
}

__global__ void transpose_split_kernel(const float* __restrict__ src,
                                       __nv_bfloat16* __restrict__ hi,
                                       __nv_bfloat16* __restrict__ lo,
                                       int K, int N)
{
    __shared__ float tile[32][33];
    const int k0 = blockIdx.y * 32;
    const int n0 = blockIdx.x * 32;
    const int tx = threadIdx.x, ty = threadIdx.y;  // (32, 8)
#pragma unroll
    for (int i = ty; i < 32; i += 8)
        tile[i][tx] = src[(size_t)(k0 + i) * N + n0 + tx];
    __syncthreads();
#pragma unroll
    for (int i = ty; i < 32; i += 8) {
        float v = tile[tx][i];
        __nv_bfloat16 h = __float2bfloat16(v);
        size_t o = (size_t)(n0 + i) * K + k0 + tx;
        hi[o] = h;
        lo[o] = __float2bfloat16(v - __bfloat162float(h));
    }
}

// ---------------------------------------------------------------------------
// cp.async double-buffered mma.sync bf16 3-pass GEMM.
// CTA tile 128x128, BK=32. 4 warps in 2x2 grid, 64x64/warp.
// R12: B frags processed in two 32-col halves (live regs ~196, no 255 cap),
// pass-grouped MMA order (acc reuse distance 1 -> 16 instructions).
// ---------------------------------------------------------------------------
#define BK 32
#define LDS_ROW 40                 // 80B rows, 16B-aligned, conflict-free
#define G_BUF 10240                // 128*40*2
#define G_STAGE (4 * G_BUF)        // 40960
#define GEMM_SMEM (2 * G_STAGE)    // 81920

// 128 threads; sub in 0..3 covers all 128 rows x 32 cols of 4 buffers.
__device__ __forceinline__ void gemm_stage_load(
    uint32_t sb,
    const __nv_bfloat16* Ahi, const __nv_bfloat16* Alo,
    const __nv_bfloat16* Bhi, const __nv_bfloat16* Blo,
    int m0, int n0, int k0, int tid, int sub)
{
    const int K = CC;
    const int idx = sub * 128 + tid;   // 0..511
    const int r = idx >> 2;
    const int c = (idx & 3) * 8;
    const uint32_t so = (uint32_t)(r * LDS_ROW + c) * 2;
    const size_t goA = (size_t)(m0 + r) * K + k0 + c;
    const size_t goB = (size_t)(n0 + r) * K + k0 + c;
    cp16(sb + 0 * G_BUF + so, Ahi + goA);
    cp16(sb + 1 * G_BUF + so, Alo + goA);
    cp16(sb + 2 * G_BUF + so, Bhi + goB);
    cp16(sb + 3 * G_BUF + so, Blo + goB);
}

__global__ __launch_bounds__(128, 2) void tc_gemm_kernel(
    const __nv_bfloat16* __restrict__ Ahi, const __nv_bfloat16* __restrict__ Alo,
    const __nv_bfloat16* __restrict__ Bhi, const __nv_bfloat16* __restrict__ Blo,
    const float* __restrict__ bias, float* __restrict__ Cout,
    int N, int mode)
{
    extern __shared__ __align__(16) char dsm[];
    const uint32_t sb0 = smem_u32(dsm);

    const int tid = threadIdx.x;
    const int warp = tid >> 5;
    const int lane = tid & 31;
    const int warpM = warp >> 1;        // 0..1 (64 rows each)
    const int warpN = warp & 1;         // 0..1 (64 cols each)
    const int m0 = blockIdx.y * 128;
    const int n0 = blockIdx.x * 128;

    float acc[4][8][4];                 // mt x nt x frag
#pragma unroll
    for (int mt = 0; mt < 4; mt++)
#pragma unroll
        for (int nt = 0; nt < 8; nt++)
#pragma unroll
            for (int i = 0; i < 4; i++) acc[mt][nt][i] = 0.0f;

    const int aRow = warpM * 64 + (lane & 15);
    const int aK   = (lane >> 4) * 8;
    // B ldmatrix.x4: covers 16 output cols per instr (two 8-col n-tiles)
    const int bRow4 = warpN * 64 + (lane >> 4) * 8 + (lane & 7);
    const int bK4   = ((lane >> 3) & 1) * 8;

    const int NCH = CC / BK;   // 32

    gemm_stage_load(sb0, Ahi, Alo, Bhi, Blo, m0, n0, 0, tid, 0);
    gemm_stage_load(sb0, Ahi, Alo, Bhi, Blo, m0, n0, 0, tid, 1);
    gemm_stage_load(sb0, Ahi, Alo, Bhi, Blo, m0, n0, 0, tid, 2);
    gemm_stage_load(sb0, Ahi, Alo, Bhi, Blo, m0, n0, 0, tid, 3);
    cp_commit();

    for (int ch = 0; ch < NCH; ch++) {
        cp_wait<0>();
        __syncthreads();

        const uint32_t st = sb0 + (ch & 1) * G_STAGE;
        const uint32_t sa_hi = st, sa_lo = st + G_BUF;
        const uint32_t sb_hi = st + 2 * G_BUF, sb_lo = st + 3 * G_BUF;
        const bool pf = (ch + 1 < NCH);
        const uint32_t pb = sb0 + ((ch + 1) & 1) * G_STAGE;

        // first half of next-chunk prefetch (R7 placement)
        if (pf) {
            gemm_stage_load(pb, Ahi, Alo, Bhi, Blo, m0, n0, (ch + 1) * BK, tid, 0);
            gemm_stage_load(pb, Ahi, Alo, Bhi, Blo, m0, n0, (ch + 1) * BK, tid, 1);
        }

#pragma unroll
        for (int ks = 0; ks < 2; ks++) {
            const int kk = ks * 16;
            uint32_t afh[4][4], afl[4][4];
#pragma unroll
            for (int mt = 0; mt < 4; mt++) {
                const uint32_t off = ((aRow + mt * 16) * LDS_ROW + aK + kk) * 2;
                ldmatrix_x4(afh[mt], sa_hi + off);
                ldmatrix_x4(afl[mt], sa_lo + off);
            }
            // process the 64-col warp-N extent in two 32-col halves:
            // live B regs halved (16 vs 32), pass-grouped MMA order inside.
#pragma unroll
            for (int half = 0; half < 2; half++) {
                uint32_t bfh[2][4], bfl[2][4];
#pragma unroll
                for (int bp = 0; bp < 2; bp++) {
                    const uint32_t off =
                        ((bRow4 + (half * 2 + bp) * 16) * LDS_ROW + bK4 + kk) * 2;
                    ldmatrix_x4(bfh[bp], sb_hi + off);
                    ldmatrix_x4(bfl[bp], sb_lo + off);
                }
                // pass 1: hi * hi  (16 independent accumulators)
#pragma unroll
                for (int mt = 0; mt < 4; mt++)
#pragma unroll
                    for (int q = 0; q < 4; q++)
                        mma_bf16(acc[mt][half * 4 + q], afh[mt],
                                 bfh[q >> 1] + (q & 1) * 2);
                // pass 2: hi * lo
#pragma unroll
                for (int mt = 0; mt < 4; mt++)
#pragma unroll
                    for (int q = 0; q < 4; q++)
                        mma_bf16(acc[mt][half * 4 + q], afh[mt],
                                 bfl[q >> 1] + (q & 1) * 2);
                // pass 3: lo * hi
#pragma unroll
                for (int mt = 0; mt < 4; mt++)
#pragma unroll
                    for (int q = 0; q < 4; q++)
                        mma_bf16(acc[mt][half * 4 + q], afl[mt],
                                 bfh[q >> 1] + (q & 1) * 2);
            }
            if (ks == 0) {
                if (pf) {
                    gemm_stage_load(pb, Ahi, Alo, Bhi, Blo, m0, n0,
                                    (ch + 1) * BK, tid, 2);
                    gemm_stage_load(pb, Ahi, Alo, Bhi, Blo, m0, n0,
                                    (ch + 1) * BK, tid, 3);
                }
                cp_commit();
            }
        }
    }

    // epilogue
#pragma unroll
    for (int mt = 0; mt < 4; mt++) {
#pragma unroll
        for (int i = 0; i < 2; i++) {
            const int m = m0 + warpM * 64 + mt * 16 + (lane >> 2) + i * 8;
            const int b = m >> 11;
            const int t = m & 2047;
#pragma unroll
            for (int nt = 0; nt < 8; nt++) {
                const int n = n0 + warpN * 64 + nt * 8 + (lane & 3) * 2;
                const float v0 = acc[mt][nt][i * 2 + 0] + bias[n];
                const float v1 = acc[mt][nt][i * 2 + 1] + bias[n + 1];
                if (mode == 0) {
                    const int region = n >> 10;      // 0=q 1=k 2=v
                    const int cc = n & 1023;
                    const int h = cc >> 6;
                    const int dd = cc & 63;
                    __nv_bfloat16* dh = (region == 0) ? g_qh
                                      : (region == 1) ? g_kh : g_vh;
                    __nv_bfloat16* dl = (region == 0) ? g_ql
                                      : (region == 1) ? g_kl : g_vl;
                    const size_t o = (((size_t)b * HH + h) * TT + t) * DD + dd;
                    const float h0 = __bfloat162float(__float2bfloat16(v0));
                    const float h1 = __bfloat162float(__float2bfloat16(v1));
                    *(uint32_t*)(dh + o) = pack_bf16(v0, v1);
                    *(uint32_t*)(dl + o) = pack_bf16(v0 - h0, v1 - h1);
                } else {
                    float2 w; w.x = v0; w.y = v1;
                    *(float2*)(Cout + (size_t)m * N + n) = w;
                }
            }
        }
    }
}

// ---------------------------------------------------------------------------
// cp.async double-buffered tensor-core flash attention (hi/lo compensated).
// Exact Round-7/11 version (passing, rel_err 1.66e-5).
// ---------------------------------------------------------------------------
#define KVROW 72
#define A_BUF (64 * KVROW * 2)
#define A_STAGE (4 * A_BUF + 256)
#define ATTN_SMEM (2 * A_STAGE)

__device__ __forceinline__ void attn_stage_load(
    uint32_t sb,
    const __nv_bfloat16* Kh, const __nv_bfloat16* Kl,
    const __nv_bfloat16* Vh, const __nv_bfloat16* Vl,
    const float* amp, int k0, int tid)
{
    const int r = tid >> 2;
    const int s2 = (tid & 3) * 2;
#pragma unroll
    for (int i = 0; i < 2; i++) {
        const int seg = s2 + i;
        const uint32_t so = (uint32_t)(r * KVROW + seg * 8) * 2;
        const size_t go = (size_t)(k0 + r) * DD + seg * 8;
        cp16(sb + 0 * A_BUF + so, Kh + go);
        cp16(sb + 1 * A_BUF + so, Kl + go);
        cp16(sb + 2 * A_BUF + so, Vh + go);
        cp16(sb + 3 * A_BUF + so, Vl + go);
    }
    if (tid < 16) cp16(sb + 4 * A_BUF + tid * 16, amp + k0 + tid * 4);
}

__global__ __launch_bounds__(256) void attn_tc_kernel(const float* __restrict__ am)
{
    extern __shared__ __align__(16) char dsm[];
    const uint32_t sb0 = smem_u32(dsm);

    const int tid = threadIdx.x;
    const int warp = tid >> 5;
    const int lane = tid & 31;
    const int g = lane >> 2;
    const int c = lane & 3;
    const int bh = blockIdx.y;
    const int b = bh >> 4;
    const int h = bh & 15;
    const int qtile = gridDim.x - 1 - blockIdx.x;
    const int q0 = qtile * 128;

    const int r1 = q0 + warp * 16 + g;
    const int r2 = r1 + 8;

    const __nv_bfloat16* Qh = g_qh + (size_t)bh * TT * DD;
    const __nv_bfloat16* Ql = g_ql + (size_t)bh * TT * DD;
    const __nv_bfloat16* Kh = g_kh + (size_t)bh * TT * DD;
    const __nv_bfloat16* Kl = g_kl + (size_t)bh * TT * DD;
    const __nv_bfloat16* Vh = g_vh + (size_t)bh * TT * DD;
    const __nv_bfloat16* Vl = g_vl + (size_t)bh * TT * DD;
    const float* amp = am + b * TT;

    uint32_t qh[4][4], ql[4][4];
#pragma unroll
    for (int ks = 0; ks < 4; ks++) {
#pragma unroll
        for (int half = 0; half < 2; half++) {
            const int col = ks * 16 + half * 8 + c * 2;
            qh[ks][half * 2 + 0] = *(const uint32_t*)(Qh + (size_t)r1 * DD + col);
            qh[ks][half * 2 + 1] = *(const uint32_t*)(Qh + (size_t)r2 * DD + col);
            ql[ks][half * 2 + 0] = *(const uint32_t*)(Ql + (size_t)r1 * DD + col);
            ql[ks][half * 2 + 1] = *(const uint32_t*)(Ql + (size_t)r2 * DD + col);
        }
    }

    float o[8][4];
#pragma unroll
    for (int nt = 0; nt < 8; nt++)
#pragma unroll
        for (int i = 0; i < 4; i++) o[nt][i] = 0.0f;
    float m0v = -1e30f, m1v = -1e30f;
    float l0 = 0.0f, l1 = 0.0f;

    const int g4 = lane >> 3;
    const int l8 = lane & 7;

    const int nkv = 2 * (qtile + 1);
    attn_stage_load(sb0, Kh, Kl, Vh, Vl, amp, 0, tid);
    cp_commit();

    for (int kt = 0; kt < nkv; kt++) {
        const int k0 = kt * 64;
        cp_wait<0>();
        __syncthreads();

        const uint32_t st = sb0 + (kt & 1) * A_STAGE;
        const uint32_t skh = st, skl = st + A_BUF;
        const uint32_t svh = st + 2 * A_BUF, svl = st + 3 * A_BUF;
        const float* amS = (const float*)(dsm + (kt & 1) * A_STAGE + 4 * A_BUF);
        const bool needCausal = (kt >= 2 * qtile);

        if (kt + 1 < nkv)
            attn_stage_load(sb0 + ((kt + 1) & 1) * A_STAGE,
                            Kh, Kl, Vh, Vl, amp, (kt + 1) * 64, tid);
        cp_commit();

        float s[8][4];
#pragma unroll
        for (int nt = 0; nt < 8; nt++)
#pragma unroll
            for (int i = 0; i < 4; i++) s[nt][i] = 0.0f;

#pragma unroll
        for (int ks = 0; ks < 4; ks++) {
#pragma unroll
            for (int nt2 = 0; nt2 < 4; nt2++) {
                const uint32_t off =
                    ((nt2 * 16 + (g4 >> 1) * 8 + l8) * KVROW +
                     ks * 16 + (g4 & 1) * 8) * 2;
                uint32_t bhf[4], blf[4];
                ldmatrix_x4(bhf, skh + off);
                ldmatrix_x4(blf, skl + off);
                mma_bf16(s[nt2 * 2 + 0], qh[ks], bhf);
                mma_bf16(s[nt2 * 2 + 1], qh[ks], bhf + 2);
                mma_bf16(s[nt2 * 2 + 0], qh[ks], blf);
                mma_bf16(s[nt2 * 2 + 1], qh[ks], blf + 2);
                mma_bf16(s[nt2 * 2 + 0], ql[ks], bhf);
                mma_bf16(s[nt2 * 2 + 1], ql[ks], bhf + 2);
            }
        }

#pragma unroll
        for (int nt = 0; nt < 8; nt++) {
            const int colb = nt * 8 + c * 2;
            const float a0 = amS[colb] * NEGINF;
            const float a1 = amS[colb + 1] * NEGINF;
            s[nt][0] = s[nt][0] * 0.125f + a0;
            s[nt][1] = s[nt][1] * 0.125f + a1;
            s[nt][2] = s[nt][2] * 0.125f + a0;
            s[nt][3] = s[nt][3] * 0.125f + a1;
            if (needCausal) {
                const int kg0 = k0 + colb;
                if (kg0 > r1)     s[nt][0] = -1e30f;
                if (kg0 + 1 > r1) s[nt][1] = -1e30f;
                if (kg0 > r2)     s[nt][2] = -1e30f;
                if (kg0 + 1 > r2) s[nt][3] = -1e30f;
            }
        }

        float t0 = -1e30f, t1 = -1e30f;
#pragma unroll
        for (int nt = 0; nt < 8; nt++) {
            t0 = fmaxf(t0, fmaxf(s[nt][0], s[nt][1]));
            t1 = fmaxf(t1, fmaxf(s[nt][2], s[nt][3]));
        }
        t0 = fmaxf(t0, __shfl_xor_sync(0xffffffffu, t0, 1));
        t0 = fmaxf(t0, __shfl_xor_sync(0xffffffffu, t0, 2));
        t1 = fmaxf(t1, __shfl_xor_sync(0xffffffffu, t1, 1));
        t1 = fmaxf(t1, __shfl_xor_sync(0xffffffffu, t1, 2));

        const float mn0 = fmaxf(m0v, t0);
        const float mn1 = fmaxf(m1v, t1);
        const float cr0 = __expf(m0v - mn0);
        const float cr1 = __expf(m1v - mn1);
        m0v = mn0; m1v = mn1;

        float s0 = 0.0f, s1 = 0.0f;
#pragma unroll
        for (int nt = 0; nt < 8; nt++) {
            s[nt][0] = __expf(s[nt][0] - mn0);
            s[nt][1] = __expf(s[nt][1] - mn0);
            s[nt][2] = __expf(s[nt][2] - mn1);
            s[nt][3] = __expf(s[nt][3] - mn1);
            s0 += s[nt][0] + s[nt][1];
            s1 += s[nt][2] + s[nt][3];
            o[nt][0] *= cr0; o[nt][1] *= cr0;
            o[nt][2] *= cr1; o[nt][3] *= cr1;
        }
        s0 += __shfl_xor_sync(0xffffffffu, s0, 1);
        s0 += __shfl_xor_sync(0xffffffffu, s0, 2);
        s1 += __shfl_xor_sync(0xffffffffu, s1, 1);
        s1 += __shfl_xor_sync(0xffffffffu, s1, 2);
        l0 = l0 * cr0 + s0;
        l1 = l1 * cr1 + s1;

#pragma unroll
        for (int j = 0; j < 4; j++) {
            uint32_t pfh[4], pfl[4];
            {
                const float p00 = s[2 * j][0],     p01 = s[2 * j][1];
                const float p10 = s[2 * j][2],     p11 = s[2 * j][3];
                const float p20 = s[2 * j + 1][0], p21 = s[2 * j + 1][1];
                const float p30 = s[2 * j + 1][2], p31 = s[2 * j + 1][3];
                const float h00 = __bfloat162float(__float2bfloat16(p00));
                const float h01 = __bfloat162float(__float2bfloat16(p01));
                const float h10 = __bfloat162float(__float2bfloat16(p10));
                const float h11 = __bfloat162float(__float2bfloat16(p11));
                const float h20 = __bfloat162float(__float2bfloat16(p20));
                const float h21 = __bfloat162float(__float2bfloat16(p21));
                const float h30 = __bfloat162float(__float2bfloat16(p30));
                const float h31 = __bfloat162float(__float2bfloat16(p31));
                pfh[0] = pack_bf16(p00, p01);
                pfh[1] = pack_bf16(p10, p11);
                pfh[2] = pack_bf16(p20, p21);
                pfh[3] = pack_bf16(p30, p31);
                pfl[0] = pack_bf16(p00 - h00, p01 - h01);
                pfl[1] = pack_bf16(p10 - h10, p11 - h11);
                pfl[2] = pack_bf16(p20 - h20, p21 - h21);
                pfl[3] = pack_bf16(p30 - h30, p31 - h31);
            }
#pragma unroll
            for (int nt2 = 0; nt2 < 4; nt2++) {
                const uint32_t off =
                    ((16 * j + (g4 & 1) * 8 + l8) * KVROW +
                     nt2 * 16 + (g4 >> 1) * 8) * 2;
                uint32_t vhf[4], vlf[4];
                ldmatrix_x4_trans(vhf, svh + off);
                ldmatrix_x4_trans(vlf, svl + off);
                mma_bf16(o[nt2 * 2 + 0], pfh, vhf);
                mma_bf16(o[nt2 * 2 + 1], pfh, vhf + 2);
                mma_bf16(o[nt2 * 2 + 0], pfh, vlf);
                mma_bf16(o[nt2 * 2 + 1], pfh, vlf + 2);
                mma_bf16(o[nt2 * 2 + 0], pfl, vhf);
                mma_bf16(o[nt2 * 2 + 1], pfl, vhf + 2);
            }
        }
    }

    const float i0 = 1.0f / l0;
    const float i1 = 1.0f / l1;
    __nv_bfloat16* Yh1 = g_yh + (size_t)(b * TT + r1) * CC + h * DD;
    __nv_bfloat16* Yl1 = g_yl + (size_t)(b * TT + r1) * CC + h * DD;
    __nv_bfloat16* Yh2 = g_yh + (size_t)(b * TT + r2) * CC + h * DD;
    __nv_bfloat16* Yl2 = g_yl + (size_t)(b * TT + r2) * CC + h * DD;
#pragma unroll
    for (int nt = 0; nt < 8; nt++) {
        const int col = nt * 8 + c * 2;
        const float w0x = o[nt][0] * i0, w0y = o[nt][1] * i0;
        const float w1x = o[nt][2] * i1, w1y = o[nt][3] * i1;
        const float h0x = __bfloat162float(__float2bfloat16(w0x));
        const float h0y = __bfloat162float(__float2bfloat16(w0y));
        const float h1x = __bfloat162float(__float2bfloat16(w1x));
        const float h1y = __bfloat162float(__float2bfloat16(w1y));
        *(uint32_t*)(Yh1 + col) = pack_bf16(w0x, w0y);
        *(uint32_t*)(Yl1 + col) = pack_bf16(w0x - h0x, w0y - h0y);
        *(uint32_t*)(Yh2 + col) = pack_bf16(w1x, w1y);
        *(uint32_t*)(Yl2 + col) = pack_bf16(w1x - h1x, w1y - h1y);
    }
}

// ---------------------------------------------------------------------------
extern "C" void kernel_launch(void* const* d_in, const int* in_sizes, int n_in,
                              void* d_out, int out_size)
{
    (void)in_sizes; (void)n_in; (void)out_size;
    const float* x  = (const float*)d_in[0];   // [B,T,C]
    const float* am = (const float*)d_in[1];   // [B,T]
    const float* Wa = (const float*)d_in[2];   // [C,3C]
    const float* ba = (const float*)d_in[3];   // [3C]
    const float* Wp = (const float*)d_in[4];   // [C,C]
    const float* bp = (const float*)d_in[5];   // [C]
    float* out = (float*)d_out;                // [B,T,C]

    cudaFuncSetAttribute(tc_gemm_kernel,
                         cudaFuncAttributeMaxDynamicSharedMemorySize, GEMM_SMEM);
    cudaFuncSetAttribute(attn_tc_kernel,
                         cudaFuncAttributeMaxDynamicSharedMemorySize, ATTN_SMEM);

    __nv_bfloat16 *xh, *xl, *yh, *yl, *wah, *wal, *wph, *wpl;
    cudaGetSymbolAddress((void**)&xh,  g_xh);
    cudaGetSymbolAddress((void**)&xl,  g_xl);
    cudaGetSymbolAddress((void**)&yh,  g_yh);
    cudaGetSymbolAddress((void**)&yl,  g_yl);
    cudaGetSymbolAddress((void**)&wah, g_wah);
    cudaGetSymbolAddress((void**)&wal, g_wal);
    cudaGetSymbolAddress((void**)&wph, g_wph);
    cudaGetSymbolAddress((void**)&wpl, g_wpl);

    const int M = BB * TT;          // 4096

    split_kernel<<<(M * CC) / 256, 256>>>(x, xh, xl, M * CC);
    transpose_split_kernel<<<dim3(3 * CC / 32, CC / 32), dim3(32, 8)>>>(
        Wa, wah, wal, CC, 3 * CC);
    transpose_split_kernel<<<dim3(CC / 32, CC / 32), dim3(32, 8)>>>(
        Wp, wph, wpl, CC, CC);

    tc_gemm_kernel<<<dim3(3 * CC / 128, M / 128), 128, GEMM_SMEM>>>(
        xh, xl, wah, wal, ba, nullptr, 3 * CC, 0);

    attn_tc_kernel<<<dim3(TT / 128, BB * HH), 256, ATTN_SMEM>>>(am);

    tc_gemm_kernel<<<dim3(CC / 128, M / 128), 128, GEMM_SMEM>>>(
        yh, yl, wph, wpl, bp, out, CC, 1);
}

// round 14
// speedup vs baseline: 1.2476x; 1.0107x over previous
#include <cuda_runtime.h>
#include <cuda_bf16.h>
#include <cstdint>
#include <cstddef>

// Problem constants
#define BB 2
#define TT 2048
#define CC 1024
#define HH 16
#define DD 64
#define NEGINF (-1e10f)
#define LOG2E 1.4426950408889634f

// ---------------------------------------------------------------------------
// Device-global scratch (no allocation allowed). q/k/v/y live ONLY as
// pre-split bf16 hi/lo pairs.
// ---------------------------------------------------------------------------
__device__ __nv_bfloat16 g_qh[(size_t)BB * HH * TT * DD];
__device__ __nv_bfloat16 g_ql[(size_t)BB * HH * TT * DD];
__device__ __nv_bfloat16 g_kh[(size_t)BB * HH * TT * DD];
__device__ __nv_bfloat16 g_kl[(size_t)BB * HH * TT * DD];
__device__ __nv_bfloat16 g_vh[(size_t)BB * HH * TT * DD];
__device__ __nv_bfloat16 g_vl[(size_t)BB * HH * TT * DD];
__device__ __nv_bfloat16 g_yh[(size_t)BB * TT * CC];
__device__ __nv_bfloat16 g_yl[(size_t)BB * TT * CC];

__device__ __nv_bfloat16 g_xh[(size_t)BB * TT * CC];
__device__ __nv_bfloat16 g_xl[(size_t)BB * TT * CC];
__device__ __nv_bfloat16 g_wah[(size_t)3 * CC * CC];
__device__ __nv_bfloat16 g_wal[(size_t)3 * CC * CC];
__device__ __nv_bfloat16 g_wph[(size_t)CC * CC];
__device__ __nv_bfloat16 g_wpl[(size_t)CC * CC];

// ---------------------------------------------------------------------------
// PTX helpers (sm_80+ — legal on plain sm_100 target)
// ---------------------------------------------------------------------------
__device__ __forceinline__ uint32_t smem_u32(const void* p) {
    return (uint32_t)__cvta_generic_to_shared(p);
}
__device__ __forceinline__ void cp16(uint32_t s, const void* g) {
    asm volatile("cp.async.cg.shared.global [%0], [%1], 16;" :: "r"(s), "l"(g));
}
__device__ __forceinline__ void cp_commit() {
    asm volatile("cp.async.commit_group;" ::: "memory");
}
template <int N>
__device__ __forceinline__ void cp_wait() {
    asm volatile("cp.async.wait_group %0;" :: "n"(N) : "memory");
}
__device__ __forceinline__ void ldmatrix_x4(uint32_t* r, uint32_t addr) {
    asm volatile("ldmatrix.sync.aligned.m8n8.x4.shared.b16 {%0,%1,%2,%3}, [%4];"
                 : "=r"(r[0]), "=r"(r[1]), "=r"(r[2]), "=r"(r[3]) : "r"(addr));
}
__device__ __forceinline__ void ldmatrix_x4_trans(uint32_t* r, uint32_t addr) {
    asm volatile("ldmatrix.sync.aligned.m8n8.x4.trans.shared.b16 {%0,%1,%2,%3}, [%4];"
                 : "=r"(r[0]), "=r"(r[1]), "=r"(r[2]), "=r"(r[3]) : "r"(addr));
}
__device__ __forceinline__ void mma_bf16(float* d, const uint32_t* a,
                                         const uint32_t* b) {
    asm volatile(
        "mma.sync.aligned.m16n8k16.row.col.f32.bf16.bf16.f32 "
        "{%0,%1,%2,%3}, {%4,%5,%6,%7}, {%8,%9}, {%0,%1,%2,%3};"
        : "+f"(d[0]), "+f"(d[1]), "+f"(d[2]), "+f"(d[3])
        : "r"(a[0]), "r"(a[1]), "r"(a[2]), "r"(a[3]), "r"(b[0]), "r"(b[1]));
}
// pack two f32 as bf16x2: first arg -> low half
__device__ __forceinline__ uint32_t pack_bf16(float lo, float hi) {
    uint32_t r;
    asm("cvt.rn.bf16x2.f32 %0, %1, %2;" : "=r"(r) : "f"(hi), "f"(lo));
    return r;
}

// ---------------------------------------------------------------------------
// Convert kernels: fp32 -> (bf16 hi, bf16 lo)
// ---------------------------------------------------------------------------
__global__ void split_kernel(const float* __restrict__ src,
                             __nv_bfloat16* __restrict__ hi,
                             __nv_bfloat16* __restrict__ lo, int n)
{
    const int i = (blockIdx.x * blockDim.x + threadIdx.x) * 4;
    if (i < n) {
        float4 v = *(const float4*)(src + i);
        const float hx = __bfloat162float(__float2bfloat16(v.x));
        const float hy = __bfloat162float(__float2bfloat16(v.y));
        const float hz = __bfloat162float(__float2bfloat16(v.z));
        const float hw = __bfloat162float(__float2bfloat16(v.w));
        uint2 ho, lw;
        ho.x = pack_bf16(v.x, v.y);
        ho.y = pack_bf16(v.z, v.w);
        lw.x = pack_bf16(v.x - hx, v.y - hy);
        lw.y = pack_bf16(v.z - hz, v.w - hw);
        *(uint2*)(hi + i) = ho;
        *(uint2*)(lo + i) = lw;
    }
}

__global__ void transpose_split_kernel(const float* __restrict__ src,
                                       __nv_bfloat16* __restrict__ hi,
                                       __nv_bfloat16* __restrict__ lo,
                                       int K, int N)
{
    __shared__ float tile[32][33];
    const int k0 = blockIdx.y * 32;
    const int n0 = blockIdx.x * 32;
    const int tx = threadIdx.x, ty = threadIdx.y;  // (32, 8)
#pragma unroll
    for (int i = ty; i < 32; i += 8)
        tile[i][tx] = src[(size_t)(k0 + i) * N + n0 + tx];
    __syncthreads();
#pragma unroll
    for (int i = ty; i < 32; i += 8) {
        float v = tile[tx][i];
        __nv_bfloat16 h = __float2bfloat16(v);
        size_t o = (size_t)(n0 + i) * K + k0 + tx;
        hi[o] = h;
        lo[o] = __float2bfloat16(v - __bfloat162float(h));
    }
}

// ---------------------------------------------------------------------------
// cp.async double-buffered mma.sync bf16 3-pass GEMM (R13 best — unchanged).
// ---------------------------------------------------------------------------
#define BK 32
#define LDS_ROW 40
#define G_BUF 10240
#define G_STAGE (4 * G_BUF)
#define GEMM_SMEM (2 * G_STAGE)

__device__ __forceinline__ void gemm_stage_load(
    uint32_t sb,
    const __nv_bfloat16* Ahi, const __nv_bfloat16* Alo,
    const __nv_bfloat16* Bhi, const __nv_bfloat16* Blo,
    int m0, int n0, int k0, int tid, int sub)
{
    const int K = CC;
    const int idx = sub * 128 + tid;
    const int r = idx >> 2;
    const int c = (idx & 3) * 8;
    const uint32_t so = (uint32_t)(r * LDS_ROW + c) * 2;
    const size_t goA = (size_t)(m0 + r) * K + k0 + c;
    const size_t goB = (size_t)(n0 + r) * K + k0 + c;
    cp16(sb + 0 * G_BUF + so, Ahi + goA);
    cp16(sb + 1 * G_BUF + so, Alo + goA);
    cp16(sb + 2 * G_BUF + so, Bhi + goB);
    cp16(sb + 3 * G_BUF + so, Blo + goB);
}

__global__ __launch_bounds__(128, 2) void tc_gemm_kernel(
    const __nv_bfloat16* __restrict__ Ahi, const __nv_bfloat16* __restrict__ Alo,
    const __nv_bfloat16* __restrict__ Bhi, const __nv_bfloat16* __restrict__ Blo,
    const float* __restrict__ bias, float* __restrict__ Cout,
    int N, int mode)
{
    extern __shared__ __align__(16) char dsm[];
    const uint32_t sb0 = smem_u32(dsm);

    const int tid = threadIdx.x;
    const int warp = tid >> 5;
    const int lane = tid & 31;
    const int warpM = warp >> 1;
    const int warpN = warp & 1;
    const int m0 = blockIdx.y * 128;
    const int n0 = blockIdx.x * 128;

    float acc[4][8][4];
#pragma unroll
    for (int mt = 0; mt < 4; mt++)
#pragma unroll
        for (int nt = 0; nt < 8; nt++)
#pragma unroll
            for (int i = 0; i < 4; i++) acc[mt][nt][i] = 0.0f;

    const int aRow = warpM * 64 + (lane & 15);
    const int aK   = (lane >> 4) * 8;
    const int bRow4 = warpN * 64 + (lane >> 4) * 8 + (lane & 7);
    const int bK4   = ((lane >> 3) & 1) * 8;

    const int NCH = CC / BK;

    gemm_stage_load(sb0, Ahi, Alo, Bhi, Blo, m0, n0, 0, tid, 0);
    gemm_stage_load(sb0, Ahi, Alo, Bhi, Blo, m0, n0, 0, tid, 1);
    gemm_stage_load(sb0, Ahi, Alo, Bhi, Blo, m0, n0, 0, tid, 2);
    gemm_stage_load(sb0, Ahi, Alo, Bhi, Blo, m0, n0, 0, tid, 3);
    cp_commit();

    for (int ch = 0; ch < NCH; ch++) {
        cp_wait<0>();
        __syncthreads();

        const uint32_t st = sb0 + (ch & 1) * G_STAGE;
        const uint32_t sa_hi = st, sa_lo = st + G_BUF;
        const uint32_t sb_hi = st + 2 * G_BUF, sb_lo = st + 3 * G_BUF;
        const bool pf = (ch + 1 < NCH);
        const uint32_t pb = sb0 + ((ch + 1) & 1) * G_STAGE;

        if (pf) {
            gemm_stage_load(pb, Ahi, Alo, Bhi, Blo, m0, n0, (ch + 1) * BK, tid, 0);
            gemm_stage_load(pb, Ahi, Alo, Bhi, Blo, m0, n0, (ch + 1) * BK, tid, 1);
        }

#pragma unroll
        for (int ks = 0; ks < 2; ks++) {
            const int kk = ks * 16;
            uint32_t afh[4][4], afl[4][4];
#pragma unroll
            for (int mt = 0; mt < 4; mt++) {
                const uint32_t off = ((aRow + mt * 16) * LDS_ROW + aK + kk) * 2;
                ldmatrix_x4(afh[mt], sa_hi + off);
                ldmatrix_x4(afl[mt], sa_lo + off);
            }
#pragma unroll
            for (int half = 0; half < 2; half++) {
                uint32_t bfh[2][4], bfl[2][4];
#pragma unroll
                for (int bp = 0; bp < 2; bp++) {
                    const uint32_t off =
                        ((bRow4 + (half * 2 + bp) * 16) * LDS_ROW + bK4 + kk) * 2;
                    ldmatrix_x4(bfh[bp], sb_hi + off);
                    ldmatrix_x4(bfl[bp], sb_lo + off);
                }
#pragma unroll
                for (int mt = 0; mt < 4; mt++)
#pragma unroll
                    for (int q = 0; q < 4; q++)
                        mma_bf16(acc[mt][half * 4 + q], afh[mt],
                                 bfh[q >> 1] + (q & 1) * 2);
#pragma unroll
                for (int mt = 0; mt < 4; mt++)
#pragma unroll
                    for (int q = 0; q < 4; q++)
                        mma_bf16(acc[mt][half * 4 + q], afh[mt],
                                 bfl[q >> 1] + (q & 1) * 2);
#pragma unroll
                for (int mt = 0; mt < 4; mt++)
#pragma unroll
                    for (int q = 0; q < 4; q++)
                        mma_bf16(acc[mt][half * 4 + q], afl[mt],
                                 bfh[q >> 1] + (q & 1) * 2);
            }
            if (ks == 0) {
                if (pf) {
                    gemm_stage_load(pb, Ahi, Alo, Bhi, Blo, m0, n0,
                                    (ch + 1) * BK, tid, 2);
                    gemm_stage_load(pb, Ahi, Alo, Bhi, Blo, m0, n0,
                                    (ch + 1) * BK, tid, 3);
                }
                cp_commit();
            }
        }
    }

    // epilogue
#pragma unroll
    for (int mt = 0; mt < 4; mt++) {
#pragma unroll
        for (int i = 0; i < 2; i++) {
            const int m = m0 + warpM * 64 + mt * 16 + (lane >> 2) + i * 8;
            const int b = m >> 11;
            const int t = m & 2047;
#pragma unroll
            for (int nt = 0; nt < 8; nt++) {
                const int n = n0 + warpN * 64 + nt * 8 + (lane & 3) * 2;
                const float v0 = acc[mt][nt][i * 2 + 0] + bias[n];
                const float v1 = acc[mt][nt][i * 2 + 1] + bias[n + 1];
                if (mode == 0) {
                    const int region = n >> 10;
                    const int cc = n & 1023;
                    const int h = cc >> 6;
                    const int dd = cc & 63;
                    __nv_bfloat16* dh = (region == 0) ? g_qh
                                      : (region == 1) ? g_kh : g_vh;
                    __nv_bfloat16* dl = (region == 0) ? g_ql
                                      : (region == 1) ? g_kl : g_vl;
                    const size_t o = (((size_t)b * HH + h) * TT + t) * DD + dd;
                    const float h0 = __bfloat162float(__float2bfloat16(v0));
                    const float h1 = __bfloat162float(__float2bfloat16(v1));
                    *(uint32_t*)(dh + o) = pack_bf16(v0, v1);
                    *(uint32_t*)(dl + o) = pack_bf16(v0 - h0, v1 - h1);
                } else {
                    float2 w; w.x = v0; w.y = v1;
                    *(float2*)(Cout + (size_t)m * N + n) = w;
                }
            }
        }
    }
}

// ---------------------------------------------------------------------------
// cp.async double-buffered tensor-core flash attention (hi/lo compensated).
// R14: __launch_bounds__(256,2) to pin 2 CTAs/SM; exp2-domain softmax.
// ---------------------------------------------------------------------------
#define KVROW 72
#define A_BUF (64 * KVROW * 2)
#define A_STAGE (4 * A_BUF + 256)
#define ATTN_SMEM (2 * A_STAGE)

__device__ __forceinline__ void attn_stage_load(
    uint32_t sb,
    const __nv_bfloat16* Kh, const __nv_bfloat16* Kl,
    const __nv_bfloat16* Vh, const __nv_bfloat16* Vl,
    const float* amp, int k0, int tid)
{
    const int r = tid >> 2;
    const int s2 = (tid & 3) * 2;
#pragma unroll
    for (int i = 0; i < 2; i++) {
        const int seg = s2 + i;
        const uint32_t so = (uint32_t)(r * KVROW + seg * 8) * 2;
        const size_t go = (size_t)(k0 + r) * DD + seg * 8;
        cp16(sb + 0 * A_BUF + so, Kh + go);
        cp16(sb + 1 * A_BUF + so, Kl + go);
        cp16(sb + 2 * A_BUF + so, Vh + go);
        cp16(sb + 3 * A_BUF + so, Vl + go);
    }
    if (tid < 16) cp16(sb + 4 * A_BUF + tid * 16, amp + k0 + tid * 4);
}

__global__ __launch_bounds__(256, 2) void attn_tc_kernel(const float* __restrict__ am)
{
    extern __shared__ __align__(16) char dsm[];
    const uint32_t sb0 = smem_u32(dsm);

    const int tid = threadIdx.x;
    const int warp = tid >> 5;
    const int lane = tid & 31;
    const int g = lane >> 2;
    const int c = lane & 3;
    const int bh = blockIdx.y;
    const int b = bh >> 4;
    const int h = bh & 15;
    const int qtile = gridDim.x - 1 - blockIdx.x;
    const int q0 = qtile * 128;

    const int r1 = q0 + warp * 16 + g;
    const int r2 = r1 + 8;

    const __nv_bfloat16* Qh = g_qh + (size_t)bh * TT * DD;
    const __nv_bfloat16* Ql = g_ql + (size_t)bh * TT * DD;
    const __nv_bfloat16* Kh = g_kh + (size_t)bh * TT * DD;
    const __nv_bfloat16* Kl = g_kl + (size_t)bh * TT * DD;
    const __nv_bfloat16* Vh = g_vh + (size_t)bh * TT * DD;
    const __nv_bfloat16* Vl = g_vl + (size_t)bh * TT * DD;
    const float* amp = am + b * TT;

    uint32_t qh[4][4], ql[4][4];
#pragma unroll
    for (int ks = 0; ks < 4; ks++) {
#pragma unroll
        for (int half = 0; half < 2; half++) {
            const int col = ks * 16 + half * 8 + c * 2;
            qh[ks][half * 2 + 0] = *(const uint32_t*)(Qh + (size_t)r1 * DD + col);
            qh[ks][half * 2 + 1] = *(const uint32_t*)(Qh + (size_t)r2 * DD + col);
            ql[ks][half * 2 + 0] = *(const uint32_t*)(Ql + (size_t)r1 * DD + col);
            ql[ks][half * 2 + 1] = *(const uint32_t*)(Ql + (size_t)r2 * DD + col);
        }
    }

    float o[8][4];
#pragma unroll
    for (int nt = 0; nt < 8; nt++)
#pragma unroll
        for (int i = 0; i < 4; i++) o[nt][i] = 0.0f;
    float m0v = -1e30f, m1v = -1e30f;
    float l0 = 0.0f, l1 = 0.0f;

    const int g4 = lane >> 3;
    const int l8 = lane & 7;

    // exp2-domain softmax constants
    const float SCL = 0.125f * LOG2E;          // folded score scale
    const float MSK = NEGINF * LOG2E;          // folded mask scale

    const int nkv = 2 * (qtile + 1);
    attn_stage_load(sb0, Kh, Kl, Vh, Vl, amp, 0, tid);
    cp_commit();

    for (int kt = 0; kt < nkv; kt++) {
        const int k0 = kt * 64;
        cp_wait<0>();
        __syncthreads();

        const uint32_t st = sb0 + (kt & 1) * A_STAGE;
        const uint32_t skh = st, skl = st + A_BUF;
        const uint32_t svh = st + 2 * A_BUF, svl = st + 3 * A_BUF;
        const float* amS = (const float*)(dsm + (kt & 1) * A_STAGE + 4 * A_BUF);
        const bool needCausal = (kt >= 2 * qtile);

        if (kt + 1 < nkv)
            attn_stage_load(sb0 + ((kt + 1) & 1) * A_STAGE,
                            Kh, Kl, Vh, Vl, amp, (kt + 1) * 64, tid);
        cp_commit();

        float s[8][4];
#pragma unroll
        for (int nt = 0; nt < 8; nt++)
#pragma unroll
            for (int i = 0; i < 4; i++) s[nt][i] = 0.0f;

#pragma unroll
        for (int ks = 0; ks < 4; ks++) {
#pragma unroll
            for (int nt2 = 0; nt2 < 4; nt2++) {
                const uint32_t off =
                    ((nt2 * 16 + (g4 >> 1) * 8 + l8) * KVROW +
                     ks * 16 + (g4 & 1) * 8) * 2;
                uint32_t bhf[4], blf[4];
                ldmatrix_x4(bhf, skh + off);
                ldmatrix_x4(blf, skl + off);
                mma_bf16(s[nt2 * 2 + 0], qh[ks], bhf);
                mma_bf16(s[nt2 * 2 + 1], qh[ks], bhf + 2);
                mma_bf16(s[nt2 * 2 + 0], qh[ks], blf);
                mma_bf16(s[nt2 * 2 + 1], qh[ks], blf + 2);
                mma_bf16(s[nt2 * 2 + 0], ql[ks], bhf);
                mma_bf16(s[nt2 * 2 + 1], ql[ks], bhf + 2);
            }
        }

        // scale + masks (log2 domain)
#pragma unroll
        for (int nt = 0; nt < 8; nt++) {
            const int colb = nt * 8 + c * 2;
            const float a0 = amS[colb] * MSK;
            const float a1 = amS[colb + 1] * MSK;
            s[nt][0] = s[nt][0] * SCL + a0;
            s[nt][1] = s[nt][1] * SCL + a1;
            s[nt][2] = s[nt][2] * SCL + a0;
            s[nt][3] = s[nt][3] * SCL + a1;
            if (needCausal) {
                const int kg0 = k0 + colb;
                if (kg0 > r1)     s[nt][0] = -1e30f;
                if (kg0 + 1 > r1) s[nt][1] = -1e30f;
                if (kg0 > r2)     s[nt][2] = -1e30f;
                if (kg0 + 1 > r2) s[nt][3] = -1e30f;
            }
        }

        // online softmax (log2 domain)
        float t0 = -1e30f, t1 = -1e30f;
#pragma unroll
        for (int nt = 0; nt < 8; nt++) {
            t0 = fmaxf(t0, fmaxf(s[nt][0], s[nt][1]));
            t1 = fmaxf(t1, fmaxf(s[nt][2], s[nt][3]));
        }
        t0 = fmaxf(t0, __shfl_xor_sync(0xffffffffu, t0, 1));
        t0 = fmaxf(t0, __shfl_xor_sync(0xffffffffu, t0, 2));
        t1 = fmaxf(t1, __shfl_xor_sync(0xffffffffu, t1, 1));
        t1 = fmaxf(t1, __shfl_xor_sync(0xffffffffu, t1, 2));

        const float mn0 = fmaxf(m0v, t0);
        const float mn1 = fmaxf(m1v, t1);
        const float cr0 = exp2f(m0v - mn0);
        const float cr1 = exp2f(m1v - mn1);
        m0v = mn0; m1v = mn1;

        float s0 = 0.0f, s1 = 0.0f;
#pragma unroll
        for (int nt = 0; nt < 8; nt++) {
            s[nt][0] = exp2f(s[nt][0] - mn0);
            s[nt][1] = exp2f(s[nt][1] - mn0);
            s[nt][2] = exp2f(s[nt][2] - mn1);
            s[nt][3] = exp2f(s[nt][3] - mn1);
            s0 += s[nt][0] + s[nt][1];
            s1 += s[nt][2] + s[nt][3];
            o[nt][0] *= cr0; o[nt][1] *= cr0;
            o[nt][2] *= cr1; o[nt][3] *= cr1;
        }
        s0 += __shfl_xor_sync(0xffffffffu, s0, 1);
        s0 += __shfl_xor_sync(0xffffffffu, s0, 2);
        s1 += __shfl_xor_sync(0xffffffffu, s1, 1);
        s1 += __shfl_xor_sync(0xffffffffu, s1, 2);
        l0 = l0 * cr0 + s0;
        l1 = l1 * cr1 + s1;

        // O += P @ V (3-term)
#pragma unroll
        for (int j = 0; j < 4; j++) {
            uint32_t pfh[4], pfl[4];
            {
                const float p00 = s[2 * j][0],     p01 = s[2 * j][1];
                const float p10 = s[2 * j][2],     p11 = s[2 * j][3];
                const float p20 = s[2 * j + 1][0], p21 = s[2 * j + 1][1];
                const float p30 = s[2 * j + 1][2], p31 = s[2 * j + 1][3];
                const float h00 = __bfloat162float(__float2bfloat16(p00));
                const float h01 = __bfloat162float(__float2bfloat16(p01));
                const float h10 = __bfloat162float(__float2bfloat16(p10));
                const float h11 = __bfloat162float(__float2bfloat16(p11));
                const float h20 = __bfloat162float(__float2bfloat16(p20));
                const float h21 = __bfloat162float(__float2bfloat16(p21));
                const float h30 = __bfloat162float(__float2bfloat16(p30));
                const float h31 = __bfloat162float(__float2bfloat16(p31));
                pfh[0] = pack_bf16(p00, p01);
                pfh[1] = pack_bf16(p10, p11);
                pfh[2] = pack_bf16(p20, p21);
                pfh[3] = pack_bf16(p30, p31);
                pfl[0] = pack_bf16(p00 - h00, p01 - h01);
                pfl[1] = pack_bf16(p10 - h10, p11 - h11);
                pfl[2] = pack_bf16(p20 - h20, p21 - h21);
                pfl[3] = pack_bf16(p30 - h30, p31 - h31);
            }
#pragma unroll
            for (int nt2 = 0; nt2 < 4; nt2++) {
                const uint32_t off =
                    ((16 * j + (g4 & 1) * 8 + l8) * KVROW +
                     nt2 * 16 + (g4 >> 1) * 8) * 2;
                uint32_t vhf[4], vlf[4];
                ldmatrix_x4_trans(vhf, svh + off);
                ldmatrix_x4_trans(vlf, svl + off);
                mma_bf16(o[nt2 * 2 + 0], pfh, vhf);
                mma_bf16(o[nt2 * 2 + 1], pfh, vhf + 2);
                mma_bf16(o[nt2 * 2 + 0], pfh, vlf);
                mma_bf16(o[nt2 * 2 + 1], pfh, vlf + 2);
                mma_bf16(o[nt2 * 2 + 0], pfl, vhf);
                mma_bf16(o[nt2 * 2 + 1], pfl, vhf + 2);
            }
        }
    }

    const float i0 = 1.0f / l0;
    const float i1 = 1.0f / l1;
    __nv_bfloat16* Yh1 = g_yh + (size_t)(b * TT + r1) * CC + h * DD;
    __nv_bfloat16* Yl1 = g_yl + (size_t)(b * TT + r1) * CC + h * DD;
    __nv_bfloat16* Yh2 = g_yh + (size_t)(b * TT + r2) * CC + h * DD;
    __nv_bfloat16* Yl2 = g_yl + (size_t)(b * TT + r2) * CC + h * DD;
#pragma unroll
    for (int nt = 0; nt < 8; nt++) {
        const int col = nt * 8 + c * 2;
        const float w0x = o[nt][0] * i0, w0y = o[nt][1] * i0;
        const float w1x = o[nt][2] * i1, w1y = o[nt][3] * i1;
        const float h0x = __bfloat162float(__float2bfloat16(w0x));
        const float h0y = __bfloat162float(__float2bfloat16(w0y));
        const float h1x = __bfloat162float(__float2bfloat16(w1x));
        const float h1y = __bfloat162float(__float2bfloat16(w1y));
        *(uint32_t*)(Yh1 + col) = pack_bf16(w0x, w0y);
        *(uint32_t*)(Yl1 + col) = pack_bf16(w0x - h0x, w0y - h0y);
        *(uint32_t*)(Yh2 + col) = pack_bf16(w1x, w1y);
        *(uint32_t*)(Yl2 + col) = pack_bf16(w1x - h1x, w1y - h1y);
    }
}

// ---------------------------------------------------------------------------
extern "C" void kernel_launch(void* const* d_in, const int* in_sizes, int n_in,
                              void* d_out, int out_size)
{
    (void)in_sizes; (void)n_in; (void)out_size;
    const float* x  = (const float*)d_in[0];   // [B,T,C]
    const float* am = (const float*)d_in[1];   // [B,T]
    const float* Wa = (const float*)d_in[2];   // [C,3C]
    const float* ba = (const float*)d_in[3];   // [3C]
    const float* Wp = (const float*)d_in[4];   // [C,C]
    const float* bp = (const float*)d_in[5];   // [C]
    float* out = (float*)d_out;                // [B,T,C]

    cudaFuncSetAttribute(tc_gemm_kernel,
                         cudaFuncAttributeMaxDynamicSharedMemorySize, GEMM_SMEM);
    cudaFuncSetAttribute(attn_tc_kernel,
                         cudaFuncAttributeMaxDynamicSharedMemorySize, ATTN_SMEM);

    __nv_bfloat16 *xh, *xl, *yh, *yl, *wah, *wal, *wph, *wpl;
    cudaGetSymbolAddress((void**)&xh,  g_xh);
    cudaGetSymbolAddress((void**)&xl,  g_xl);
    cudaGetSymbolAddress((void**)&yh,  g_yh);
    cudaGetSymbolAddress((void**)&yl,  g_yl);
    cudaGetSymbolAddress((void**)&wah, g_wah);
    cudaGetSymbolAddress((void**)&wal, g_wal);
    cudaGetSymbolAddress((void**)&wph, g_wph);
    cudaGetSymbolAddress((void**)&wpl, g_wpl);

    const int M = BB * TT;          // 4096

    split_kernel<<<(M * CC / 4) / 256, 256>>>(x, xh, xl, M * CC);
    transpose_split_kernel<<<dim3(3 * CC / 32, CC / 32), dim3(32, 8)>>>(
        Wa, wah, wal, CC, 3 * CC);
    transpose_split_kernel<<<dim3(CC / 32, CC / 32), dim3(32, 8)>>>(
        Wp, wph, wpl, CC, CC);

    tc_gemm_kernel<<<dim3(3 * CC / 128, M / 128), 128, GEMM_SMEM>>>(
        xh, xl, wah, wal, ba, nullptr, 3 * CC, 0);

    attn_tc_kernel<<<dim3(TT / 128, BB * HH), 256, ATTN_SMEM>>>(am);

    tc_gemm_kernel<<<dim3(CC / 128, M / 128), 128, GEMM_SMEM>>>(
        yh, yl, wph, wpl, bp, out, CC, 1);
}

// round 16
// speedup vs baseline: 1.7935x; 1.4375x over previous
#include <cuda_runtime.h>
#include <cuda_fp16.h>
#include <cstdint>
#include <cstddef>

// Problem constants
#define BB 2
#define TT 2048
#define CC 1024
#define HH 16
#define DD 64
#define NEGINF (-1e10f)
#define LOG2E 1.4426950408889634f

// ---------------------------------------------------------------------------
// Device-global scratch. fp16 2-pass scheme: A-side operands single fp16
// (x, q, y), B-side operands split fp16 hi/lo (weights, k, v).
// ---------------------------------------------------------------------------
__device__ __half g_q [(size_t)BB * HH * TT * DD];
__device__ __half g_kh[(size_t)BB * HH * TT * DD];
__device__ __half g_kl[(size_t)BB * HH * TT * DD];
__device__ __half g_vh[(size_t)BB * HH * TT * DD];
__device__ __half g_vl[(size_t)BB * HH * TT * DD];
__device__ __half g_y [(size_t)BB * TT * CC];

__device__ __half g_x  [(size_t)BB * TT * CC];
__device__ __half g_wah[(size_t)3 * CC * CC];
__device__ __half g_wal[(size_t)3 * CC * CC];
__device__ __half g_wph[(size_t)CC * CC];
__device__ __half g_wpl[(size_t)CC * CC];

// ---------------------------------------------------------------------------
// PTX helpers (sm_80+ — legal on plain sm_100 target)
// ---------------------------------------------------------------------------
__device__ __forceinline__ uint32_t smem_u32(const void* p) {
    return (uint32_t)__cvta_generic_to_shared(p);
}
__device__ __forceinline__ void cp16(uint32_t s, const void* g) {
    asm volatile("cp.async.cg.shared.global [%0], [%1], 16;" :: "r"(s), "l"(g));
}
__device__ __forceinline__ void cp_commit() {
    asm volatile("cp.async.commit_group;" ::: "memory");
}
template <int N>
__device__ __forceinline__ void cp_wait() {
    asm volatile("cp.async.wait_group %0;" :: "n"(N) : "memory");
}
__device__ __forceinline__ void ldmatrix_x4(uint32_t* r, uint32_t addr) {
    asm volatile("ldmatrix.sync.aligned.m8n8.x4.shared.b16 {%0,%1,%2,%3}, [%4];"
                 : "=r"(r[0]), "=r"(r[1]), "=r"(r[2]), "=r"(r[3]) : "r"(addr));
}
__device__ __forceinline__ void ldmatrix_x4_trans(uint32_t* r, uint32_t addr) {
    asm volatile("ldmatrix.sync.aligned.m8n8.x4.trans.shared.b16 {%0,%1,%2,%3}, [%4];"
                 : "=r"(r[0]), "=r"(r[1]), "=r"(r[2]), "=r"(r[3]) : "r"(addr));
}
__device__ __forceinline__ void mma_f16(float* d, const uint32_t* a,
                                        const uint32_t* b) {
    asm volatile(
        "mma.sync.aligned.m16n8k16.row.col.f32.f16.f16.f32 "
        "{%0,%1,%2,%3}, {%4,%5,%6,%7}, {%8,%9}, {%0,%1,%2,%3};"
        : "+f"(d[0]), "+f"(d[1]), "+f"(d[2]), "+f"(d[3])
        : "r"(a[0]), "r"(a[1]), "r"(a[2]), "r"(a[3]), "r"(b[0]), "r"(b[1]));
}
// pack two f32 as f16x2: first arg -> low half
__device__ __forceinline__ uint32_t pack_f16(float lo, float hi) {
    uint32_t r;
    asm("cvt.rn.f16x2.f32 %0, %1, %2;" : "=r"(r) : "f"(hi), "f"(lo));
    return r;
}

// ---------------------------------------------------------------------------
// Convert kernels
// ---------------------------------------------------------------------------
// fp32 -> fp16 single (vectorized 4/thread)
__global__ void convert_kernel(const float* __restrict__ src,
                               __half* __restrict__ dst, int n)
{
    const int i = (blockIdx.x * blockDim.x + threadIdx.x) * 4;
    if (i < n) {
        float4 v = *(const float4*)(src + i);
        uint2 o;
        o.x = pack_f16(v.x, v.y);
        o.y = pack_f16(v.z, v.w);
        *(uint2*)(dst + i) = o;
    }
}

// src [K,N] row-major -> out [N,K] (transposed) split into fp16 hi/lo
__global__ void transpose_split_kernel(const float* __restrict__ src,
                                       __half* __restrict__ hi,
                                       __half* __restrict__ lo,
                                       int K, int N)
{
    __shared__ float tile[32][33];
    const int k0 = blockIdx.y * 32;
    const int n0 = blockIdx.x * 32;
    const int tx = threadIdx.x, ty = threadIdx.y;  // (32, 8)
#pragma unroll
    for (int i = ty; i < 32; i += 8)
        tile[i][tx] = src[(size_t)(k0 + i) * N + n0 + tx];
    __syncthreads();
#pragma unroll
    for (int i = ty; i < 32; i += 8) {
        float v = tile[tx][i];
        __half h = __float2half_rn(v);
        size_t o = (size_t)(n0 + i) * K + k0 + tx;
        hi[o] = h;
        lo[o] = __float2half_rn(v - __half2float(h));
    }
}

// ---------------------------------------------------------------------------
// cp.async double-buffered mma.sync fp16 2-pass GEMM.
// D[M,N] = A[M,K] @ B^T[N,K] + bias.  A single fp16; B split hi/lo.
// CTA tile 128x128, BK=32, 4 warps (2x2), 64x64/warp. 3 smem buffers/stage.
// mode 0: q -> single fp16, k/v -> fp16 hi/lo pairs. mode 1: fp32 out.
// ---------------------------------------------------------------------------
#define BK 32
#define LDS_ROW 40                 // 80B rows, 16B-aligned, conflict-free
#define G_BUF 10240                // 128*40*2
#define G_STAGE (3 * G_BUF)        // 30720
#define GEMM_SMEM (2 * G_STAGE)    // 61440

__device__ __forceinline__ void gemm_stage_load(
    uint32_t sb,
    const __half* A, const __half* Bh, const __half* Bl,
    int m0, int n0, int k0, int tid, int sub)
{
    const int K = CC;
    const int idx = sub * 128 + tid;   // 0..511
    const int r = idx >> 2;
    const int c = (idx & 3) * 8;
    const uint32_t so = (uint32_t)(r * LDS_ROW + c) * 2;
    const size_t goA = (size_t)(m0 + r) * K + k0 + c;
    const size_t goB = (size_t)(n0 + r) * K + k0 + c;
    cp16(sb + 0 * G_BUF + so, A + goA);
    cp16(sb + 1 * G_BUF + so, Bh + goB);
    cp16(sb + 2 * G_BUF + so, Bl + goB);
}

__global__ __launch_bounds__(128, 2) void tc_gemm_kernel(
    const __half* __restrict__ A,
    const __half* __restrict__ Bh, const __half* __restrict__ Bl,
    const float* __restrict__ bias, float* __restrict__ Cout,
    int N, int mode)
{
    extern __shared__ __align__(16) char dsm[];
    const uint32_t sb0 = smem_u32(dsm);

    const int tid = threadIdx.x;
    const int warp = tid >> 5;
    const int lane = tid & 31;
    const int warpM = warp >> 1;
    const int warpN = warp & 1;
    const int m0 = blockIdx.y * 128;
    const int n0 = blockIdx.x * 128;

    float acc[4][8][4];
#pragma unroll
    for (int mt = 0; mt < 4; mt++)
#pragma unroll
        for (int nt = 0; nt < 8; nt++)
#pragma unroll
            for (int i = 0; i < 4; i++) acc[mt][nt][i] = 0.0f;

    const int aRow = warpM * 64 + (lane & 15);
    const int aK   = (lane >> 4) * 8;
    const int bRow4 = warpN * 64 + (lane >> 4) * 8 + (lane & 7);
    const int bK4   = ((lane >> 3) & 1) * 8;

    const int NCH = CC / BK;

    gemm_stage_load(sb0, A, Bh, Bl, m0, n0, 0, tid, 0);
    gemm_stage_load(sb0, A, Bh, Bl, m0, n0, 0, tid, 1);
    gemm_stage_load(sb0, A, Bh, Bl, m0, n0, 0, tid, 2);
    gemm_stage_load(sb0, A, Bh, Bl, m0, n0, 0, tid, 3);
    cp_commit();

    for (int ch = 0; ch < NCH; ch++) {
        cp_wait<0>();
        __syncthreads();

        const uint32_t st = sb0 + (ch & 1) * G_STAGE;
        const uint32_t sa = st;
        const uint32_t sb_hi = st + 1 * G_BUF, sb_lo = st + 2 * G_BUF;
        const bool pf = (ch + 1 < NCH);
        const uint32_t pb = sb0 + ((ch + 1) & 1) * G_STAGE;

        if (pf) {
            gemm_stage_load(pb, A, Bh, Bl, m0, n0, (ch + 1) * BK, tid, 0);
            gemm_stage_load(pb, A, Bh, Bl, m0, n0, (ch + 1) * BK, tid, 1);
        }

#pragma unroll
        for (int ks = 0; ks < 2; ks++) {
            const int kk = ks * 16;
            uint32_t af[4][4];
#pragma unroll
            for (int mt = 0; mt < 4; mt++) {
                const uint32_t off = ((aRow + mt * 16) * LDS_ROW + aK + kk) * 2;
                ldmatrix_x4(af[mt], sa + off);
            }
#pragma unroll
            for (int half = 0; half < 2; half++) {
                uint32_t bfh[2][4], bfl[2][4];
#pragma unroll
                for (int bp = 0; bp < 2; bp++) {
                    const uint32_t off =
                        ((bRow4 + (half * 2 + bp) * 16) * LDS_ROW + bK4 + kk) * 2;
                    ldmatrix_x4(bfh[bp], sb_hi + off);
                    ldmatrix_x4(bfl[bp], sb_lo + off);
                }
                // pass 1: A * Bhi
#pragma unroll
                for (int mt = 0; mt < 4; mt++)
#pragma unroll
                    for (int q = 0; q < 4; q++)
                        mma_f16(acc[mt][half * 4 + q], af[mt],
                                bfh[q >> 1] + (q & 1) * 2);
                // pass 2: A * Blo
#pragma unroll
                for (int mt = 0; mt < 4; mt++)
#pragma unroll
                    for (int q = 0; q < 4; q++)
                        mma_f16(acc[mt][half * 4 + q], af[mt],
                                bfl[q >> 1] + (q & 1) * 2);
            }
            if (ks == 0) {
                if (pf) {
                    gemm_stage_load(pb, A, Bh, Bl, m0, n0, (ch + 1) * BK, tid, 2);
                    gemm_stage_load(pb, A, Bh, Bl, m0, n0, (ch + 1) * BK, tid, 3);
                }
                cp_commit();
            }
        }
    }

    // epilogue
#pragma unroll
    for (int mt = 0; mt < 4; mt++) {
#pragma unroll
        for (int i = 0; i < 2; i++) {
            const int m = m0 + warpM * 64 + mt * 16 + (lane >> 2) + i * 8;
            const int b = m >> 11;
            const int t = m & 2047;
#pragma unroll
            for (int nt = 0; nt < 8; nt++) {
                const int n = n0 + warpN * 64 + nt * 8 + (lane & 3) * 2;
                const float v0 = acc[mt][nt][i * 2 + 0] + bias[n];
                const float v1 = acc[mt][nt][i * 2 + 1] + bias[n + 1];
                if (mode == 0) {
                    const int region = n >> 10;      // 0=q 1=k 2=v
                    const int cc = n & 1023;
                    const int h = cc >> 6;
                    const int dd = cc & 63;
                    const size_t o = (((size_t)b * HH + h) * TT + t) * DD + dd;
                    if (region == 0) {
                        *(uint32_t*)(g_q + o) = pack_f16(v0, v1);
                    } else {
                        __half* dh = (region == 1) ? g_kh : g_vh;
                        __half* dl = (region == 1) ? g_kl : g_vl;
                        const float h0 = __half2float(__float2half_rn(v0));
                        const float h1 = __half2float(__float2half_rn(v1));
                        *(uint32_t*)(dh + o) = pack_f16(v0, v1);
                        *(uint32_t*)(dl + o) = pack_f16(v0 - h0, v1 - h1);
                    }
                } else {
                    float2 w; w.x = v0; w.y = v1;
                    *(float2*)(Cout + (size_t)m * N + n) = w;
                }
            }
        }
    }
}

// ---------------------------------------------------------------------------
// cp.async double-buffered tensor-core flash attention (fp16 2-pass).
// Q single fp16; K, V split fp16 hi/lo; P single fp16 (no Pl pass).
// ---------------------------------------------------------------------------
#define KVROW 72
#define A_BUF (64 * KVROW * 2)
#define A_STAGE (4 * A_BUF + 256)
#define ATTN_SMEM (2 * A_STAGE)

__device__ __forceinline__ void attn_stage_load(
    uint32_t sb,
    const __half* Kh, const __half* Kl,
    const __half* Vh, const __half* Vl,
    const float* amp, int k0, int tid)
{
    const int r = tid >> 2;
    const int s2 = (tid & 3) * 2;
#pragma unroll
    for (int i = 0; i < 2; i++) {
        const int seg = s2 + i;
        const uint32_t so = (uint32_t)(r * KVROW + seg * 8) * 2;
        const size_t go = (size_t)(k0 + r) * DD + seg * 8;
        cp16(sb + 0 * A_BUF + so, Kh + go);
        cp16(sb + 1 * A_BUF + so, Kl + go);
        cp16(sb + 2 * A_BUF + so, Vh + go);
        cp16(sb + 3 * A_BUF + so, Vl + go);
    }
    if (tid < 16) cp16(sb + 4 * A_BUF + tid * 16, amp + k0 + tid * 4);
}

__global__ __launch_bounds__(256, 2) void attn_tc_kernel(const float* __restrict__ am)
{
    extern __shared__ __align__(16) char dsm[];
    const uint32_t sb0 = smem_u32(dsm);

    const int tid = threadIdx.x;
    const int warp = tid >> 5;
    const int lane = tid & 31;
    const int g = lane >> 2;
    const int c = lane & 3;
    const int bh = blockIdx.y;
    const int b = bh >> 4;
    const int h = bh & 15;
    const int qtile = gridDim.x - 1 - blockIdx.x;
    const int q0 = qtile * 128;

    const int r1 = q0 + warp * 16 + g;
    const int r2 = r1 + 8;

    const __half* Qp = g_q + (size_t)bh * TT * DD;
    const __half* Kh = g_kh + (size_t)bh * TT * DD;
    const __half* Kl = g_kl + (size_t)bh * TT * DD;
    const __half* Vh = g_vh + (size_t)bh * TT * DD;
    const __half* Vl = g_vl + (size_t)bh * TT * DD;
    const float* amp = am + b * TT;

    // Q fragments: single fp16
    uint32_t qf[4][4];
#pragma unroll
    for (int ks = 0; ks < 4; ks++) {
#pragma unroll
        for (int half = 0; half < 2; half++) {
            const int col = ks * 16 + half * 8 + c * 2;
            qf[ks][half * 2 + 0] = *(const uint32_t*)(Qp + (size_t)r1 * DD + col);
            qf[ks][half * 2 + 1] = *(const uint32_t*)(Qp + (size_t)r2 * DD + col);
        }
    }

    float o[8][4];
#pragma unroll
    for (int nt = 0; nt < 8; nt++)
#pragma unroll
        for (int i = 0; i < 4; i++) o[nt][i] = 0.0f;
    float m0v = -1e30f, m1v = -1e30f;
    float l0 = 0.0f, l1 = 0.0f;

    const int g4 = lane >> 3;
    const int l8 = lane & 7;

    const float SCL = 0.125f * LOG2E;
    const float MSK = NEGINF * LOG2E;

    const int nkv = 2 * (qtile + 1);
    attn_stage_load(sb0, Kh, Kl, Vh, Vl, amp, 0, tid);
    cp_commit();

    for (int kt = 0; kt < nkv; kt++) {
        const int k0 = kt * 64;
        cp_wait<0>();
        __syncthreads();

        const uint32_t st = sb0 + (kt & 1) * A_STAGE;
        const uint32_t skh = st, skl = st + A_BUF;
        const uint32_t svh = st + 2 * A_BUF, svl = st + 3 * A_BUF;
        const float* amS = (const float*)(dsm + (kt & 1) * A_STAGE + 4 * A_BUF);
        const bool needCausal = (kt >= 2 * qtile);

        if (kt + 1 < nkv)
            attn_stage_load(sb0 + ((kt + 1) & 1) * A_STAGE,
                            Kh, Kl, Vh, Vl, amp, (kt + 1) * 64, tid);
        cp_commit();

        // --- S = Q @ (Kh + Kl)^T  (2-pass)
        float s[8][4];
#pragma unroll
        for (int nt = 0; nt < 8; nt++)
#pragma unroll
            for (int i = 0; i < 4; i++) s[nt][i] = 0.0f;

#pragma unroll
        for (int ks = 0; ks < 4; ks++) {
#pragma unroll
            for (int nt2 = 0; nt2 < 4; nt2++) {
                const uint32_t off =
                    ((nt2 * 16 + (g4 >> 1) * 8 + l8) * KVROW +
                     ks * 16 + (g4 & 1) * 8) * 2;
                uint32_t bhf[4], blf[4];
                ldmatrix_x4(bhf, skh + off);
                ldmatrix_x4(blf, skl + off);
                mma_f16(s[nt2 * 2 + 0], qf[ks], bhf);
                mma_f16(s[nt2 * 2 + 1], qf[ks], bhf + 2);
                mma_f16(s[nt2 * 2 + 0], qf[ks], blf);
                mma_f16(s[nt2 * 2 + 1], qf[ks], blf + 2);
            }
        }

        // scale + masks (log2 domain)
#pragma unroll
        for (int nt = 0; nt < 8; nt++) {
            const int colb = nt * 8 + c * 2;
            const float a0 = amS[colb] * MSK;
            const float a1 = amS[colb + 1] * MSK;
            s[nt][0] = s[nt][0] * SCL + a0;
            s[nt][1] = s[nt][1] * SCL + a1;
            s[nt][2] = s[nt][2] * SCL + a0;
            s[nt][3] = s[nt][3] * SCL + a1;
            if (needCausal) {
                const int kg0 = k0 + colb;
                if (kg0 > r1)     s[nt][0] = -1e30f;
                if (kg0 + 1 > r1) s[nt][1] = -1e30f;
                if (kg0 > r2)     s[nt][2] = -1e30f;
                if (kg0 + 1 > r2) s[nt][3] = -1e30f;
            }
        }

        // online softmax (log2 domain)
        float t0 = -1e30f, t1 = -1e30f;
#pragma unroll
        for (int nt = 0; nt < 8; nt++) {
            t0 = fmaxf(t0, fmaxf(s[nt][0], s[nt][1]));
            t1 = fmaxf(t1, fmaxf(s[nt][2], s[nt][3]));
        }
        t0 = fmaxf(t0, __shfl_xor_sync(0xffffffffu, t0, 1));
        t0 = fmaxf(t0, __shfl_xor_sync(0xffffffffu, t0, 2));
        t1 = fmaxf(t1, __shfl_xor_sync(0xffffffffu, t1, 1));
        t1 = fmaxf(t1, __shfl_xor_sync(0xffffffffu, t1, 2));

        const float mn0 = fmaxf(m0v, t0);
        const float mn1 = fmaxf(m1v, t1);
        const float cr0 = exp2f(m0v - mn0);
        const float cr1 = exp2f(m1v - mn1);
        m0v = mn0; m1v = mn1;

        float s0 = 0.0f, s1 = 0.0f;
#pragma unroll
        for (int nt = 0; nt < 8; nt++) {
            s[nt][0] = exp2f(s[nt][0] - mn0);
            s[nt][1] = exp2f(s[nt][1] - mn0);
            s[nt][2] = exp2f(s[nt][2] - mn1);
            s[nt][3] = exp2f(s[nt][3] - mn1);
            s0 += s[nt][0] + s[nt][1];
            s1 += s[nt][2] + s[nt][3];
            o[nt][0] *= cr0; o[nt][1] *= cr0;
            o[nt][2] *= cr1; o[nt][3] *= cr1;
        }
        s0 += __shfl_xor_sync(0xffffffffu, s0, 1);
        s0 += __shfl_xor_sync(0xffffffffu, s0, 2);
        s1 += __shfl_xor_sync(0xffffffffu, s1, 1);
        s1 += __shfl_xor_sync(0xffffffffu, s1, 2);
        l0 = l0 * cr0 + s0;
        l1 = l1 * cr1 + s1;

        // --- O += P @ (Vh + Vl)  (P single fp16, 2-pass)
#pragma unroll
        for (int j = 0; j < 4; j++) {
            uint32_t pfh[4];
            pfh[0] = pack_f16(s[2 * j][0],     s[2 * j][1]);
            pfh[1] = pack_f16(s[2 * j][2],     s[2 * j][3]);
            pfh[2] = pack_f16(s[2 * j + 1][0], s[2 * j + 1][1]);
            pfh[3] = pack_f16(s[2 * j + 1][2], s[2 * j + 1][3]);
#pragma unroll
            for (int nt2 = 0; nt2 < 4; nt2++) {
                const uint32_t off =
                    ((16 * j + (g4 & 1) * 8 + l8) * KVROW +
                     nt2 * 16 + (g4 >> 1) * 8) * 2;
                uint32_t vhf[4], vlf[4];
                ldmatrix_x4_trans(vhf, svh + off);
                ldmatrix_x4_trans(vlf, svl + off);
                mma_f16(o[nt2 * 2 + 0], pfh, vhf);
                mma_f16(o[nt2 * 2 + 1], pfh, vhf + 2);
                mma_f16(o[nt2 * 2 + 0], pfh, vlf);
                mma_f16(o[nt2 * 2 + 1], pfh, vlf + 2);
            }
        }
    }

    // epilogue: normalize, write y single fp16
    const float i0 = 1.0f / l0;
    const float i1 = 1.0f / l1;
    __half* Y1 = g_y + (size_t)(b * TT + r1) * CC + h * DD;
    __half* Y2 = g_y + (size_t)(b * TT + r2) * CC + h * DD;
#pragma unroll
    for (int nt = 0; nt < 8; nt++) {
        const int col = nt * 8 + c * 2;
        *(uint32_t*)(Y1 + col) = pack_f16(o[nt][0] * i0, o[nt][1] * i0);
        *(uint32_t*)(Y2 + col) = pack_f16(o[nt][2] * i1, o[nt][3] * i1);
    }
}

// ---------------------------------------------------------------------------
extern "C" void kernel_launch(void* const* d_in, const int* in_sizes, int n_in,
                              void* d_out, int out_size)
{
    (void)in_sizes; (void)n_in; (void)out_size;
    const float* x  = (const float*)d_in[0];   // [B,T,C]
    const float* am = (const float*)d_in[1];   // [B,T]
    const float* Wa = (const float*)d_in[2];   // [C,3C]
    const float* ba = (const float*)d_in[3];   // [3C]
    const float* Wp = (const float*)d_in[4];   // [C,C]
    const float* bp = (const float*)d_in[5];   // [C]
    float* out = (float*)d_out;                // [B,T,C]

    cudaFuncSetAttribute(tc_gemm_kernel,
                         cudaFuncAttributeMaxDynamicSharedMemorySize, GEMM_SMEM);
    cudaFuncSetAttribute(attn_tc_kernel,
                         cudaFuncAttributeMaxDynamicSharedMemorySize, ATTN_SMEM);

    __half *xp, *yp, *wah, *wal, *wph, *wpl;
    cudaGetSymbolAddress((void**)&xp,  g_x);
    cudaGetSymbolAddress((void**)&yp,  g_y);
    cudaGetSymbolAddress((void**)&wah, g_wah);
    cudaGetSymbolAddress((void**)&wal, g_wal);
    cudaGetSymbolAddress((void**)&wph, g_wph);
    cudaGetSymbolAddress((void**)&wpl, g_wpl);

    const int M = BB * TT;          // 4096

    // 0) operand conversion
    convert_kernel<<<(M * CC / 4) / 256, 256>>>(x, xp, M * CC);
    transpose_split_kernel<<<dim3(3 * CC / 32, CC / 32), dim3(32, 8)>>>(
        Wa, wah, wal, CC, 3 * CC);
    transpose_split_kernel<<<dim3(CC / 32, CC / 32), dim3(32, 8)>>>(
        Wp, wph, wpl, CC, CC);

    // 1) QKV projection (fp16 2-pass) -> q single, k/v pairs [B,H,T,D]
    tc_gemm_kernel<<<dim3(3 * CC / 128, M / 128), 128, GEMM_SMEM>>>(
        xp, wah, wal, ba, nullptr, 3 * CC, 0);

    // 2) flash attention (fp16 2-pass) -> y single fp16 [B,T,C]
    attn_tc_kernel<<<dim3(TT / 128, BB * HH), 256, ATTN_SMEM>>>(am);

    // 3) output projection (fp16 2-pass) -> d_out fp32
    tc_gemm_kernel<<<dim3(CC / 128, M / 128), 128, GEMM_SMEM>>>(
        yp, wph, wpl, bp, out, CC, 1);
}

// round 17
// speedup vs baseline: 2.2461x; 1.2524x over previous
#include <cuda_runtime.h>
#include <cuda_fp16.h>
#include <cstdint>
#include <cstddef>

// Problem constants
#define BB 2
#define TT 2048
#define CC 1024
#define HH 16
#define DD 64
#define NEGINF (-1e10f)
#define LOG2E 1.4426950408889634f

// ---------------------------------------------------------------------------
// Device-global scratch. fp16 scheme: activations single fp16 (x,q,k,v,y),
// weights split fp16 hi/lo (compensated).
// ---------------------------------------------------------------------------
__device__ __half g_q [(size_t)BB * HH * TT * DD];
__device__ __half g_k [(size_t)BB * HH * TT * DD];
__device__ __half g_v [(size_t)BB * HH * TT * DD];
__device__ __half g_y [(size_t)BB * TT * CC];

__device__ __half g_x  [(size_t)BB * TT * CC];
__device__ __half g_wah[(size_t)3 * CC * CC];
__device__ __half g_wal[(size_t)3 * CC * CC];
__device__ __half g_wph[(size_t)CC * CC];
__device__ __half g_wpl[(size_t)CC * CC];

// ---------------------------------------------------------------------------
// PTX helpers (sm_80+ — legal on plain sm_100 target)
// ---------------------------------------------------------------------------
__device__ __forceinline__ uint32_t smem_u32(const void* p) {
    return (uint32_t)__cvta_generic_to_shared(p);
}
__device__ __forceinline__ void cp16(uint32_t s, const void* g) {
    asm volatile("cp.async.cg.shared.global [%0], [%1], 16;" :: "r"(s), "l"(g));
}
__device__ __forceinline__ void cp_commit() {
    asm volatile("cp.async.commit_group;" ::: "memory");
}
template <int N>
__device__ __forceinline__ void cp_wait() {
    asm volatile("cp.async.wait_group %0;" :: "n"(N) : "memory");
}
__device__ __forceinline__ void ldmatrix_x4(uint32_t* r, uint32_t addr) {
    asm volatile("ldmatrix.sync.aligned.m8n8.x4.shared.b16 {%0,%1,%2,%3}, [%4];"
                 : "=r"(r[0]), "=r"(r[1]), "=r"(r[2]), "=r"(r[3]) : "r"(addr));
}
__device__ __forceinline__ void ldmatrix_x4_trans(uint32_t* r, uint32_t addr) {
    asm volatile("ldmatrix.sync.aligned.m8n8.x4.trans.shared.b16 {%0,%1,%2,%3}, [%4];"
                 : "=r"(r[0]), "=r"(r[1]), "=r"(r[2]), "=r"(r[3]) : "r"(addr));
}
__device__ __forceinline__ void mma_f16(float* d, const uint32_t* a,
                                        const uint32_t* b) {
    asm volatile(
        "mma.sync.aligned.m16n8k16.row.col.f32.f16.f16.f32 "
        "{%0,%1,%2,%3}, {%4,%5,%6,%7}, {%8,%9}, {%0,%1,%2,%3};"
        : "+f"(d[0]), "+f"(d[1]), "+f"(d[2]), "+f"(d[3])
        : "r"(a[0]), "r"(a[1]), "r"(a[2]), "r"(a[3]), "r"(b[0]), "r"(b[1]));
}
// pack two f32 as f16x2: first arg -> low half
__device__ __forceinline__ uint32_t pack_f16(float lo, float hi) {
    uint32_t r;
    asm("cvt.rn.f16x2.f32 %0, %1, %2;" : "=r"(r) : "f"(hi), "f"(lo));
    return r;
}

// ---------------------------------------------------------------------------
// Convert kernels
// ---------------------------------------------------------------------------
__global__ void convert_kernel(const float* __restrict__ src,
                               __half* __restrict__ dst, int n)
{
    const int i = (blockIdx.x * blockDim.x + threadIdx.x) * 4;
    if (i < n) {
        float4 v = *(const float4*)(src + i);
        uint2 o;
        o.x = pack_f16(v.x, v.y);
        o.y = pack_f16(v.z, v.w);
        *(uint2*)(dst + i) = o;
    }
}

// src [K,N] row-major -> out [N,K] (transposed) split into fp16 hi/lo
__global__ void transpose_split_kernel(const float* __restrict__ src,
                                       __half* __restrict__ hi,
                                       __half* __restrict__ lo,
                                       int K, int N)
{
    __shared__ float tile[32][33];
    const int k0 = blockIdx.y * 32;
    const int n0 = blockIdx.x * 32;
    const int tx = threadIdx.x, ty = threadIdx.y;  // (32, 8)
#pragma unroll
    for (int i = ty; i < 32; i += 8)
        tile[i][tx] = src[(size_t)(k0 + i) * N + n0 + tx];
    __syncthreads();
#pragma unroll
    for (int i = ty; i < 32; i += 8) {
        float v = tile[tx][i];
        __half h = __float2half_rn(v);
        size_t o = (size_t)(n0 + i) * K + k0 + tx;
        hi[o] = h;
        lo[o] = __float2half_rn(v - __half2float(h));
    }
}

// ---------------------------------------------------------------------------
// cp.async double-buffered mma.sync fp16 2-pass GEMM (unchanged from R16).
// A single fp16; B (weights) split hi/lo. mode 0: q/k/v single fp16 out.
// ---------------------------------------------------------------------------
#define BK 32
#define LDS_ROW 40
#define G_BUF 10240
#define G_STAGE (3 * G_BUF)        // 30720
#define GEMM_SMEM (2 * G_STAGE)    // 61440

__device__ __forceinline__ void gemm_stage_load(
    uint32_t sb,
    const __half* A, const __half* Bh, const __half* Bl,
    int m0, int n0, int k0, int tid, int sub)
{
    const int K = CC;
    const int idx = sub * 128 + tid;
    const int r = idx >> 2;
    const int c = (idx & 3) * 8;
    const uint32_t so = (uint32_t)(r * LDS_ROW + c) * 2;
    const size_t goA = (size_t)(m0 + r) * K + k0 + c;
    const size_t goB = (size_t)(n0 + r) * K + k0 + c;
    cp16(sb + 0 * G_BUF + so, A + goA);
    cp16(sb + 1 * G_BUF + so, Bh + goB);
    cp16(sb + 2 * G_BUF + so, Bl + goB);
}

__global__ __launch_bounds__(128, 2) void tc_gemm_kernel(
    const __half* __restrict__ A,
    const __half* __restrict__ Bh, const __half* __restrict__ Bl,
    const float* __restrict__ bias, float* __restrict__ Cout,
    int N, int mode)
{
    extern __shared__ __align__(16) char dsm[];
    const uint32_t sb0 = smem_u32(dsm);

    const int tid = threadIdx.x;
    const int warp = tid >> 5;
    const int lane = tid & 31;
    const int warpM = warp >> 1;
    const int warpN = warp & 1;
    const int m0 = blockIdx.y * 128;
    const int n0 = blockIdx.x * 128;

    float acc[4][8][4];
#pragma unroll
    for (int mt = 0; mt < 4; mt++)
#pragma unroll
        for (int nt = 0; nt < 8; nt++)
#pragma unroll
            for (int i = 0; i < 4; i++) acc[mt][nt][i] = 0.0f;

    const int aRow = warpM * 64 + (lane & 15);
    const int aK   = (lane >> 4) * 8;
    const int bRow4 = warpN * 64 + (lane >> 4) * 8 + (lane & 7);
    const int bK4   = ((lane >> 3) & 1) * 8;

    const int NCH = CC / BK;

    gemm_stage_load(sb0, A, Bh, Bl, m0, n0, 0, tid, 0);
    gemm_stage_load(sb0, A, Bh, Bl, m0, n0, 0, tid, 1);
    gemm_stage_load(sb0, A, Bh, Bl, m0, n0, 0, tid, 2);
    gemm_stage_load(sb0, A, Bh, Bl, m0, n0, 0, tid, 3);
    cp_commit();

    for (int ch = 0; ch < NCH; ch++) {
        cp_wait<0>();
        __syncthreads();

        const uint32_t st = sb0 + (ch & 1) * G_STAGE;
        const uint32_t sa = st;
        const uint32_t sb_hi = st + 1 * G_BUF, sb_lo = st + 2 * G_BUF;
        const bool pf = (ch + 1 < NCH);
        const uint32_t pb = sb0 + ((ch + 1) & 1) * G_STAGE;

        if (pf) {
            gemm_stage_load(pb, A, Bh, Bl, m0, n0, (ch + 1) * BK, tid, 0);
            gemm_stage_load(pb, A, Bh, Bl, m0, n0, (ch + 1) * BK, tid, 1);
        }

#pragma unroll
        for (int ks = 0; ks < 2; ks++) {
            const int kk = ks * 16;
            uint32_t af[4][4];
#pragma unroll
            for (int mt = 0; mt < 4; mt++) {
                const uint32_t off = ((aRow + mt * 16) * LDS_ROW + aK + kk) * 2;
                ldmatrix_x4(af[mt], sa + off);
            }
#pragma unroll
            for (int half = 0; half < 2; half++) {
                uint32_t bfh[2][4], bfl[2][4];
#pragma unroll
                for (int bp = 0; bp < 2; bp++) {
                    const uint32_t off =
                        ((bRow4 + (half * 2 + bp) * 16) * LDS_ROW + bK4 + kk) * 2;
                    ldmatrix_x4(bfh[bp], sb_hi + off);
                    ldmatrix_x4(bfl[bp], sb_lo + off);
                }
#pragma unroll
                for (int mt = 0; mt < 4; mt++)
#pragma unroll
                    for (int q = 0; q < 4; q++)
                        mma_f16(acc[mt][half * 4 + q], af[mt],
                                bfh[q >> 1] + (q & 1) * 2);
#pragma unroll
                for (int mt = 0; mt < 4; mt++)
#pragma unroll
                    for (int q = 0; q < 4; q++)
                        mma_f16(acc[mt][half * 4 + q], af[mt],
                                bfl[q >> 1] + (q & 1) * 2);
            }
            if (ks == 0) {
                if (pf) {
                    gemm_stage_load(pb, A, Bh, Bl, m0, n0, (ch + 1) * BK, tid, 2);
                    gemm_stage_load(pb, A, Bh, Bl, m0, n0, (ch + 1) * BK, tid, 3);
                }
                cp_commit();
            }
        }
    }

    // epilogue
#pragma unroll
    for (int mt = 0; mt < 4; mt++) {
#pragma unroll
        for (int i = 0; i < 2; i++) {
            const int m = m0 + warpM * 64 + mt * 16 + (lane >> 2) + i * 8;
            const int b = m >> 11;
            const int t = m & 2047;
#pragma unroll
            for (int nt = 0; nt < 8; nt++) {
                const int n = n0 + warpN * 64 + nt * 8 + (lane & 3) * 2;
                const float v0 = acc[mt][nt][i * 2 + 0] + bias[n];
                const float v1 = acc[mt][nt][i * 2 + 1] + bias[n + 1];
                if (mode == 0) {
                    const int region = n >> 10;      // 0=q 1=k 2=v
                    const int cc = n & 1023;
                    const int h = cc >> 6;
                    const int dd = cc & 63;
                    const size_t o = (((size_t)b * HH + h) * TT + t) * DD + dd;
                    __half* dst = (region == 0) ? g_q
                                : (region == 1) ? g_k : g_v;
                    *(uint32_t*)(dst + o) = pack_f16(v0, v1);
                } else {
                    float2 w; w.x = v0; w.y = v1;
                    *(float2*)(Cout + (size_t)m * N + n) = w;
                }
            }
        }
    }
}

// ---------------------------------------------------------------------------
// cp.async double-buffered tensor-core flash attention (all-fp16 single
// operands inside attention; weights-only compensation elsewhere).
// ---------------------------------------------------------------------------
#define KVROW 72
#define A_BUF (64 * KVROW * 2)       // 9216
#define A_STAGE (2 * A_BUF + 256)    // 18688 (am tile at +18432)
#define ATTN_SMEM (2 * A_STAGE)      // 37376

__device__ __forceinline__ void attn_stage_load(
    uint32_t sb,
    const __half* Kp, const __half* Vp,
    const float* amp, int k0, int tid)
{
    const int r = tid >> 2;
    const int s2 = (tid & 3) * 2;
#pragma unroll
    for (int i = 0; i < 2; i++) {
        const int seg = s2 + i;
        const uint32_t so = (uint32_t)(r * KVROW + seg * 8) * 2;
        const size_t go = (size_t)(k0 + r) * DD + seg * 8;
        cp16(sb + 0 * A_BUF + so, Kp + go);
        cp16(sb + 1 * A_BUF + so, Vp + go);
    }
    if (tid < 16) cp16(sb + 2 * A_BUF + tid * 16, amp + k0 + tid * 4);
}

__global__ __launch_bounds__(256, 2) void attn_tc_kernel(const float* __restrict__ am)
{
    extern __shared__ __align__(16) char dsm[];
    const uint32_t sb0 = smem_u32(dsm);

    const int tid = threadIdx.x;
    const int warp = tid >> 5;
    const int lane = tid & 31;
    const int g = lane >> 2;
    const int c = lane & 3;
    const int bh = blockIdx.y;
    const int b = bh >> 4;
    const int h = bh & 15;
    const int qtile = gridDim.x - 1 - blockIdx.x;
    const int q0 = qtile * 128;

    const int r1 = q0 + warp * 16 + g;
    const int r2 = r1 + 8;

    const __half* Qp = g_q + (size_t)bh * TT * DD;
    const __half* Kp = g_k + (size_t)bh * TT * DD;
    const __half* Vp = g_v + (size_t)bh * TT * DD;
    const float* amp = am + b * TT;

    uint32_t qf[4][4];
#pragma unroll
    for (int ks = 0; ks < 4; ks++) {
#pragma unroll
        for (int half = 0; half < 2; half++) {
            const int col = ks * 16 + half * 8 + c * 2;
            qf[ks][half * 2 + 0] = *(const uint32_t*)(Qp + (size_t)r1 * DD + col);
            qf[ks][half * 2 + 1] = *(const uint32_t*)(Qp + (size_t)r2 * DD + col);
        }
    }

    float o[8][4];
#pragma unroll
    for (int nt = 0; nt < 8; nt++)
#pragma unroll
        for (int i = 0; i < 4; i++) o[nt][i] = 0.0f;
    float m0v = -1e30f, m1v = -1e30f;
    float l0 = 0.0f, l1 = 0.0f;

    const int g4 = lane >> 3;
    const int l8 = lane & 7;

    const float SCL = 0.125f * LOG2E;
    const float MSK = NEGINF * LOG2E;

    const int nkv = 2 * (qtile + 1);
    attn_stage_load(sb0, Kp, Vp, amp, 0, tid);
    cp_commit();

    for (int kt = 0; kt < nkv; kt++) {
        const int k0 = kt * 64;
        cp_wait<0>();
        __syncthreads();

        const uint32_t st = sb0 + (kt & 1) * A_STAGE;
        const uint32_t sk = st, sv = st + A_BUF;
        const float* amS = (const float*)(dsm + (kt & 1) * A_STAGE + 2 * A_BUF);
        const bool needCausal = (kt >= 2 * qtile);

        if (kt + 1 < nkv)
            attn_stage_load(sb0 + ((kt + 1) & 1) * A_STAGE,
                            Kp, Vp, amp, (kt + 1) * 64, tid);
        cp_commit();

        // --- S = Q @ K^T (single pass)
        float s[8][4];
#pragma unroll
        for (int nt = 0; nt < 8; nt++)
#pragma unroll
            for (int i = 0; i < 4; i++) s[nt][i] = 0.0f;

#pragma unroll
        for (int ks = 0; ks < 4; ks++) {
#pragma unroll
            for (int nt2 = 0; nt2 < 4; nt2++) {
                const uint32_t off =
                    ((nt2 * 16 + (g4 >> 1) * 8 + l8) * KVROW +
                     ks * 16 + (g4 & 1) * 8) * 2;
                uint32_t kf[4];
                ldmatrix_x4(kf, sk + off);
                mma_f16(s[nt2 * 2 + 0], qf[ks], kf);
                mma_f16(s[nt2 * 2 + 1], qf[ks], kf + 2);
            }
        }

        // scale + masks (log2 domain)
#pragma unroll
        for (int nt = 0; nt < 8; nt++) {
            const int colb = nt * 8 + c * 2;
            const float a0 = amS[colb] * MSK;
            const float a1 = amS[colb + 1] * MSK;
            s[nt][0] = s[nt][0] * SCL + a0;
            s[nt][1] = s[nt][1] * SCL + a1;
            s[nt][2] = s[nt][2] * SCL + a0;
            s[nt][3] = s[nt][3] * SCL + a1;
            if (needCausal) {
                const int kg0 = k0 + colb;
                if (kg0 > r1)     s[nt][0] = -1e30f;
                if (kg0 + 1 > r1) s[nt][1] = -1e30f;
                if (kg0 > r2)     s[nt][2] = -1e30f;
                if (kg0 + 1 > r2) s[nt][3] = -1e30f;
            }
        }

        // online softmax (log2 domain)
        float t0 = -1e30f, t1 = -1e30f;
#pragma unroll
        for (int nt = 0; nt < 8; nt++) {
            t0 = fmaxf(t0, fmaxf(s[nt][0], s[nt][1]));
            t1 = fmaxf(t1, fmaxf(s[nt][2], s[nt][3]));
        }
        t0 = fmaxf(t0, __shfl_xor_sync(0xffffffffu, t0, 1));
        t0 = fmaxf(t0, __shfl_xor_sync(0xffffffffu, t0, 2));
        t1 = fmaxf(t1, __shfl_xor_sync(0xffffffffu, t1, 1));
        t1 = fmaxf(t1, __shfl_xor_sync(0xffffffffu, t1, 2));

        const float mn0 = fmaxf(m0v, t0);
        const float mn1 = fmaxf(m1v, t1);
        const float cr0 = exp2f(m0v - mn0);
        const float cr1 = exp2f(m1v - mn1);
        m0v = mn0; m1v = mn1;

        float s0 = 0.0f, s1 = 0.0f;
#pragma unroll
        for (int nt = 0; nt < 8; nt++) {
            s[nt][0] = exp2f(s[nt][0] - mn0);
            s[nt][1] = exp2f(s[nt][1] - mn0);
            s[nt][2] = exp2f(s[nt][2] - mn1);
            s[nt][3] = exp2f(s[nt][3] - mn1);
            s0 += s[nt][0] + s[nt][1];
            s1 += s[nt][2] + s[nt][3];
            o[nt][0] *= cr0; o[nt][1] *= cr0;
            o[nt][2] *= cr1; o[nt][3] *= cr1;
        }
        s0 += __shfl_xor_sync(0xffffffffu, s0, 1);
        s0 += __shfl_xor_sync(0xffffffffu, s0, 2);
        s1 += __shfl_xor_sync(0xffffffffu, s1, 1);
        s1 += __shfl_xor_sync(0xffffffffu, s1, 2);
        l0 = l0 * cr0 + s0;
        l1 = l1 * cr1 + s1;

        // --- O += P @ V (single pass)
#pragma unroll
        for (int j = 0; j < 4; j++) {
            uint32_t pfh[4];
            pfh[0] = pack_f16(s[2 * j][0],     s[2 * j][1]);
            pfh[1] = pack_f16(s[2 * j][2],     s[2 * j][3]);
            pfh[2] = pack_f16(s[2 * j + 1][0], s[2 * j + 1][1]);
            pfh[3] = pack_f16(s[2 * j + 1][2], s[2 * j + 1][3]);
#pragma unroll
            for (int nt2 = 0; nt2 < 4; nt2++) {
                const uint32_t off =
                    ((16 * j + (g4 & 1) * 8 + l8) * KVROW +
                     nt2 * 16 + (g4 >> 1) * 8) * 2;
                uint32_t vf[4];
                ldmatrix_x4_trans(vf, sv + off);
                mma_f16(o[nt2 * 2 + 0], pfh, vf);
                mma_f16(o[nt2 * 2 + 1], pfh, vf + 2);
            }
        }
    }

    // epilogue: normalize, write y single fp16
    const float i0 = 1.0f / l0;
    const float i1 = 1.0f / l1;
    __half* Y1 = g_y + (size_t)(b * TT + r1) * CC + h * DD;
    __half* Y2 = g_y + (size_t)(b * TT + r2) * CC + h * DD;
#pragma unroll
    for (int nt = 0; nt < 8; nt++) {
        const int col = nt * 8 + c * 2;
        *(uint32_t*)(Y1 + col) = pack_f16(o[nt][0] * i0, o[nt][1] * i0);
        *(uint32_t*)(Y2 + col) = pack_f16(o[nt][2] * i1, o[nt][3] * i1);
    }
}

// ---------------------------------------------------------------------------
extern "C" void kernel_launch(void* const* d_in, const int* in_sizes, int n_in,
                              void* d_out, int out_size)
{
    (void)in_sizes; (void)n_in; (void)out_size;
    const float* x  = (const float*)d_in[0];   // [B,T,C]
    const float* am = (const float*)d_in[1];   // [B,T]
    const float* Wa = (const float*)d_in[2];   // [C,3C]
    const float* ba = (const float*)d_in[3];   // [3C]
    const float* Wp = (const float*)d_in[4];   // [C,C]
    const float* bp = (const float*)d_in[5];   // [C]
    float* out = (float*)d_out;                // [B,T,C]

    cudaFuncSetAttribute(tc_gemm_kernel,
                         cudaFuncAttributeMaxDynamicSharedMemorySize, GEMM_SMEM);
    cudaFuncSetAttribute(attn_tc_kernel,
                         cudaFuncAttributeMaxDynamicSharedMemorySize, ATTN_SMEM);

    __half *xp, *yp, *wah, *wal, *wph, *wpl;
    cudaGetSymbolAddress((void**)&xp,  g_x);
    cudaGetSymbolAddress((void**)&yp,  g_y);
    cudaGetSymbolAddress((void**)&wah, g_wah);
    cudaGetSymbolAddress((void**)&wal, g_wal);
    cudaGetSymbolAddress((void**)&wph, g_wph);
    cudaGetSymbolAddress((void**)&wpl, g_wpl);

    const int M = BB * TT;          // 4096

    // 0) operand conversion
    convert_kernel<<<(M * CC / 4) / 256, 256>>>(x, xp, M * CC);
    transpose_split_kernel<<<dim3(3 * CC / 32, CC / 32), dim3(32, 8)>>>(
        Wa, wah, wal, CC, 3 * CC);
    transpose_split_kernel<<<dim3(CC / 32, CC / 32), dim3(32, 8)>>>(
        Wp, wph, wpl, CC, CC);

    // 1) QKV projection (fp16 2-pass) -> q/k/v single fp16 [B,H,T,D]
    tc_gemm_kernel<<<dim3(3 * CC / 128, M / 128), 128, GEMM_SMEM>>>(
        xp, wah, wal, ba, nullptr, 3 * CC, 0);

    // 2) flash attention (fp16 single-pass K/V) -> y single fp16 [B,T,C]
    attn_tc_kernel<<<dim3(TT / 128, BB * HH), 256, ATTN_SMEM>>>(am);

    // 3) output projection (fp16 2-pass) -> d_out fp32
    tc_gemm_kernel<<<dim3(CC / 128, M / 128), 128, GEMM_SMEM>>>(
        yp, wph, wpl, bp, out, CC, 1);
}